// round 14
// baseline (speedup 1.0000x reference)
#include <cuda_runtime.h>
#include <math.h>

// Problem constants
#define BB 2
#define NN 1024
#define CSD 384
#define HH 12
#define CC 16
#define PQN 4
#define PVN 8
#define NPAD 1026        // N + 2*PAD
#define PROW 512         // num_pool
#define TT 1538          // NPAD + PROW
#define HC 192           // H*C
#define HPQ3 144         // H*PQ*3
#define HPV3 288         // H*PV*3
#define OCW 576          // HC + HPV3 + H*PV
#define ATTS 8           // split-KV: supplies 3072 warps vs 16-warp/SM reg cap
#define ACHUNK ((TT + ATTS - 1) / ATTS)   // 193
#define KED 32           // extended key dim (16 + 12 + 1 + pad)

#define C1 0.176776695f       // w_l * (1/sqrt(C))
#define WC_HALF 0.117851130f  // w_c/2

typedef unsigned long long u64;

// packed f32x2 helpers (Blackwell sm_100a+)
__device__ __forceinline__ void fma2(u64 &d, u64 a, u64 b) {
    asm("fma.rn.f32x2 %0, %1, %2, %0;" : "+l"(d) : "l"(a), "l"(b));
}
__device__ __forceinline__ void mul2ip(u64 &d, u64 a) {
    asm("mul.rn.f32x2 %0, %0, %1;" : "+l"(d) : "l"(a));
}
__device__ __forceinline__ u64 pack2(float lo, float hi) {
    u64 r; asm("mov.b64 %0, {%1, %2};" : "=l"(r) : "f"(lo), "f"(hi)); return r;
}
__device__ __forceinline__ void unpack2(u64 v, float &lo, float &hi) {
    asm("mov.b64 {%0, %1}, %2;" : "=f"(lo), "=f"(hi) : "l"(v));
}
__device__ __forceinline__ unsigned f2tf32(float v) {
    unsigned r; asm("cvt.rna.tf32.f32 %0, %1;" : "=r"(r) : "f"(v)); return r;
}

// Scratch (device globals)
__device__ float g_s_pool[BB*PROW*CSD];
__device__ float g_tP[BB*PROW*3];
__device__ float g_rP[BB*PROW*9];
__device__ float g_k0 [BB*NN*HC];
__device__ float g_v0 [BB*NN*HC];
__device__ float g_kp0[BB*NN*HPQ3];
__device__ float g_vp0[BB*NN*HPV3];
__device__ float g_kpT[BB*NN*HPQ3];
__device__ float g_vpT[BB*NN*HPV3];
__device__ float g_skR[BB*NN*HH];
__device__ float g_kP [BB*PROW*HC];
__device__ float g_vP [BB*PROW*HC];
__device__ float g_kpP[BB*PROW*HPQ3];
__device__ float g_vpP[BB*PROW*HPV3];
__device__ float g_skP[BB*PROW*HH];
__device__ float g_q  [BB*PROW*HC];
__device__ float g_qp [BB*PROW*HPQ3];
__device__ float g_wfold[6*OCW];

#define NPART (BB*PROW*HH*ATTS)
__device__ float g_pm[NPART];
__device__ float g_pl[NPART];
__device__ float g_po[NPART*CC];
__device__ float g_pg[NPART*PVN*3];

__device__ __forceinline__ int clampsrc(int e) {
    int v = e - 1;
    return v < 0 ? 0 : (v > NN - 1 ? NN - 1 : v);
}

// ---------------------------------------------------------------------------
// Prep + weight fold fused
// ---------------------------------------------------------------------------
#define SP_TOT (BB*PROW*CSD)
#define TRP_TOT (BB*PROW*12)
#define FOLD_TOT (OCW*32)
__global__ void prep_fold_kernel(const float* __restrict__ s,
                                 const float* __restrict__ trans,
                                 const float* __restrict__ rots,
                                 const float* __restrict__ wout,
                                 const float* __restrict__ wupd) {
    int idx = blockIdx.x * blockDim.x + threadIdx.x;
    if (idx < SP_TOT) {
        int c = idx % CSD;
        int bp = idx / CSD;
        int p = bp % PROW;
        int b = bp / PROW;
        g_s_pool[idx] = (s[(b * NN + clampsrc(2 * p    )) * CSD + c]
                       + s[(b * NN + clampsrc(2 * p + 1)) * CSD + c]
                       + s[(b * NN + clampsrc(2 * p + 2)) * CSD + c]) * (1.f / 3.f);
        return;
    }
    int k = idx - SP_TOT;
    if (k < TRP_TOT) {
        int d = k % 12;
        int bp = k / 12;
        int p = bp % PROW;
        int b = bp / PROW;
        int r0 = clampsrc(2 * p), r1 = clampsrc(2 * p + 1), r2 = clampsrc(2 * p + 2);
        if (d < 3) {
            g_tP[bp * 3 + d] = (trans[(b * NN + r0) * 3 + d]
                              + trans[(b * NN + r1) * 3 + d]
                              + trans[(b * NN + r2) * 3 + d]) * (1.f / 3.f);
        } else {
            int r = d - 3;
            g_rP[bp * 9 + r] = (rots[(b * NN + r0) * 9 + r]
                              + rots[(b * NN + r1) * 9 + r]
                              + rots[(b * NN + r2) * 9 + r]) * (1.f / 3.f);
        }
        return;
    }
    int fi = k - TRP_TOT;
    if (fi >= FOLD_TOT) return;
    int gw = fi >> 5;
    int lane = fi & 31;
    const float* wr = wout + (long)gw * CSD;
    float acc[6] = {0, 0, 0, 0, 0, 0};
    for (int m = lane; m < CSD; m += 32) {
        float w = wr[m];
#pragma unroll
        for (int j = 0; j < 6; j++) acc[j] += w * __ldg(&wupd[m * 6 + j]);
    }
#pragma unroll
    for (int off = 16; off > 0; off >>= 1)
#pragma unroll
        for (int j = 0; j < 6; j++)
            acc[j] += __shfl_down_sync(0xffffffffu, acc[j], off);
    if (lane == 0) {
#pragma unroll
        for (int j = 0; j < 6; j++) g_wfold[j * OCW + gw] = acc[j];
    }
}

// ---------------------------------------------------------------------------
// Fused multi-task GEMM on tensor cores (tf32 mma m16n8k8) — proven.
// ---------------------------------------------------------------------------
#define NTASK 6
struct GemmTask {
    const float* A;
    const float* B;
    float* C;
    int M, N, K, gx;
};
struct TaskPack {
    GemmTask t[NTASK];
    int ofs[NTASK + 1];
};

#define GBM 64
#define GBN 64
#define GBK 16
__global__ void mgemm_kernel(TaskPack P) {
    int bid = blockIdx.x;
    int ti = 0;
#pragma unroll
    for (int x = 0; x < NTASK - 1; x++)
        if (bid >= P.ofs[x + 1]) ti = x + 1;
    GemmTask tk = P.t[ti];
    int lb = bid - P.ofs[ti];
    int bx = lb % tk.gx, by = lb / tk.gx;

    __shared__ unsigned As[GBM][GBK + 1];
    __shared__ unsigned Bs[GBK][GBN + 8];

    int tid = threadIdx.x;
    int warp = tid >> 5, lane = tid & 31;
    int gid = lane >> 2, tig = lane & 3;
    int wm = warp & 3;
    int wn = warp >> 2;
    int row0 = by * GBM;
    int col0 = bx * GBN;
    const float* A = tk.A;
    const float* Bm = tk.B;
    int M = tk.M, Nn = tk.N, K = tk.K;

    float d[4][4];
#pragma unroll
    for (int t = 0; t < 4; t++)
#pragma unroll
        for (int c = 0; c < 4; c++) d[t][c] = 0.f;

    for (int k0 = 0; k0 < K; k0 += GBK) {
#pragma unroll
        for (int x = 0; x < 4; x++) {
            int li = tid + x * 256;
            int m = li >> 4, kk = li & 15;
            int gm = row0 + m;
            float v = (gm < M) ? A[(long)gm * K + k0 + kk] : 0.f;
            As[m][kk] = f2tf32(v);
        }
#pragma unroll
        for (int x = 0; x < 4; x++) {
            int li = tid + x * 256;
            int kk = li >> 6, n = li & 63;
            int gn = col0 + n;
            float v = (gn < Nn) ? Bm[(long)(k0 + kk) * Nn + gn] : 0.f;
            Bs[kk][n] = f2tf32(v);
        }
        __syncthreads();

#pragma unroll
        for (int ks = 0; ks < 2; ks++) {
            int kb = ks * 8;
            int ra = wm * 16 + gid;
            unsigned a0 = As[ra][kb + tig];
            unsigned a1 = As[ra + 8][kb + tig];
            unsigned a2 = As[ra][kb + tig + 4];
            unsigned a3 = As[ra + 8][kb + tig + 4];
#pragma unroll
            for (int t = 0; t < 4; t++) {
                int nb = wn * 32 + t * 8;
                unsigned b0 = Bs[kb + tig][nb + gid];
                unsigned b1 = Bs[kb + tig + 4][nb + gid];
                asm volatile(
                    "mma.sync.aligned.m16n8k8.row.col.f32.tf32.tf32.f32 "
                    "{%0,%1,%2,%3}, {%4,%5,%6,%7}, {%8,%9}, {%0,%1,%2,%3};"
                    : "+f"(d[t][0]), "+f"(d[t][1]), "+f"(d[t][2]), "+f"(d[t][3])
                    : "r"(a0), "r"(a1), "r"(a2), "r"(a3), "r"(b0), "r"(b1));
            }
        }
        __syncthreads();
    }

#pragma unroll
    for (int t = 0; t < 4; t++) {
        int gn0 = col0 + wn * 32 + t * 8 + tig * 2;
        int gm0 = row0 + wm * 16 + gid;
        if (gm0 < M) {
            if (gn0 < Nn)     tk.C[(long)gm0 * Nn + gn0]     = d[t][0];
            if (gn0 + 1 < Nn) tk.C[(long)gm0 * Nn + gn0 + 1] = d[t][1];
        }
        int gm1 = gm0 + 8;
        if (gm1 < M) {
            if (gn0 < Nn)     tk.C[(long)gm1 * Nn + gn0]     = d[t][2];
            if (gn0 + 1 < Nn) tk.C[(long)gm1 * Nn + gn0 + 1] = d[t][3];
        }
    }
}

// ---------------------------------------------------------------------------
// Transform kernel (proven), 4 ranges.
// ---------------------------------------------------------------------------
#define RAWPT (BB*NN*HH)
#define POOLKV (BB*PROW*(HC/4)*2)
#define POOLPT (BB*PROW*HH)
#define QPT (BB*PROW*HH)
#define XF_TOT (RAWPT + POOLKV + POOLPT + QPT)

__device__ __forceinline__ float4 avg3f4(float4 a, float4 b, float4 c) {
    return make_float4((a.x + b.x + c.x) * (1.f / 3.f),
                       (a.y + b.y + c.y) * (1.f / 3.f),
                       (a.z + b.z + c.z) * (1.f / 3.f),
                       (a.w + b.w + c.w) * (1.f / 3.f));
}

__global__ void transform_kernel(const float* __restrict__ trans,
                                 const float* __restrict__ rots) {
    int idx = blockIdx.x * blockDim.x + threadIdx.x;
    if (idx < RAWPT) {
        int h = idx % HH;
        int rn = idx / HH;
        float R[9], tr[3];
#pragma unroll
        for (int r = 0; r < 9; r++) R[r] = rots[rn * 9 + r];
#pragma unroll
        for (int r = 0; r < 3; r++) tr[r] = trans[rn * 3 + r];

        {
            const float4* src = reinterpret_cast<const float4*>(g_kp0 + ((long)rn * HPQ3 + h * PQN * 3));
            float lp[PQN * 3];
#pragma unroll
            for (int c = 0; c < 3; c++) {
                float4 v = src[c];
                lp[c*4+0] = v.x; lp[c*4+1] = v.y; lp[c*4+2] = v.z; lp[c*4+3] = v.w;
            }
            float sk = 0.f;
            float gp[PQN * 3];
#pragma unroll
            for (int p = 0; p < PQN; p++) {
                float lx = lp[p*3+0], ly = lp[p*3+1], lz = lp[p*3+2];
                float gx = R[0]*lx + R[1]*ly + R[2]*lz + tr[0];
                float gy = R[3]*lx + R[4]*ly + R[5]*lz + tr[1];
                float gz = R[6]*lx + R[7]*ly + R[8]*lz + tr[2];
                gp[p*3+0] = gx; gp[p*3+1] = gy; gp[p*3+2] = gz;
                sk += gx*gx + gy*gy + gz*gz;
            }
            g_skR[rn * HH + h] = sk;
            float4* dst = reinterpret_cast<float4*>(g_kpT + ((long)rn * HPQ3 + h * PQN * 3));
#pragma unroll
            for (int c = 0; c < 3; c++)
                dst[c] = make_float4(gp[c*4+0], gp[c*4+1], gp[c*4+2], gp[c*4+3]);
        }
        {
            const float4* src = reinterpret_cast<const float4*>(g_vp0 + ((long)rn * HPV3 + h * PVN * 3));
            float lp[PVN * 3];
#pragma unroll
            for (int c = 0; c < 6; c++) {
                float4 v = src[c];
                lp[c*4+0] = v.x; lp[c*4+1] = v.y; lp[c*4+2] = v.z; lp[c*4+3] = v.w;
            }
            float gp[PVN * 3];
#pragma unroll
            for (int p = 0; p < PVN; p++) {
                float lx = lp[p*3+0], ly = lp[p*3+1], lz = lp[p*3+2];
                gp[p*3+0] = R[0]*lx + R[1]*ly + R[2]*lz + tr[0];
                gp[p*3+1] = R[3]*lx + R[4]*ly + R[5]*lz + tr[1];
                gp[p*3+2] = R[6]*lx + R[7]*ly + R[8]*lz + tr[2];
            }
            float4* dst = reinterpret_cast<float4*>(g_vpT + ((long)rn * HPV3 + h * PVN * 3));
#pragma unroll
            for (int c = 0; c < 6; c++)
                dst[c] = make_float4(gp[c*4+0], gp[c*4+1], gp[c*4+2], gp[c*4+3]);
        }
        return;
    }
    int i2 = idx - RAWPT;
    if (i2 < POOLKV) {
        int c = i2 % (HC / 4);
        int rest = i2 / (HC / 4);
        int rp = rest % (BB * PROW);
        int sel = rest / (BB * PROW);
        int p = rp % PROW;
        int b = rp / PROW;
        int r0 = clampsrc(2 * p), r1 = clampsrc(2 * p + 1), r2 = clampsrc(2 * p + 2);
        const float* srcbase = sel ? g_v0 : g_k0;
        float* dstbase = sel ? g_vP : g_kP;
        float4 a = reinterpret_cast<const float4*>(srcbase + ((long)(b * NN + r0) * HC))[c];
        float4 bb = reinterpret_cast<const float4*>(srcbase + ((long)(b * NN + r1) * HC))[c];
        float4 cc = reinterpret_cast<const float4*>(srcbase + ((long)(b * NN + r2) * HC))[c];
        reinterpret_cast<float4*>(dstbase + ((long)rp * HC))[c] = avg3f4(a, bb, cc);
        return;
    }
    int i3 = i2 - POOLKV;
    if (i3 < POOLPT) {
        int h = i3 % HH;
        int rp = i3 / HH;
        int p = rp % PROW;
        int b = rp / PROW;
        int r0 = clampsrc(2 * p), r1 = clampsrc(2 * p + 1), r2 = clampsrc(2 * p + 2);
        float R[9], tr[3];
#pragma unroll
        for (int r = 0; r < 9; r++) R[r] = g_rP[rp * 9 + r];
#pragma unroll
        for (int r = 0; r < 3; r++) tr[r] = g_tP[rp * 3 + r];

        {
            float lp[PQN * 3];
            const float4* a = reinterpret_cast<const float4*>(g_kp0 + ((long)(b * NN + r0) * HPQ3 + h * PQN * 3));
            const float4* bb = reinterpret_cast<const float4*>(g_kp0 + ((long)(b * NN + r1) * HPQ3 + h * PQN * 3));
            const float4* cc = reinterpret_cast<const float4*>(g_kp0 + ((long)(b * NN + r2) * HPQ3 + h * PQN * 3));
#pragma unroll
            for (int c = 0; c < 3; c++) {
                float4 v = avg3f4(a[c], bb[c], cc[c]);
                lp[c*4+0] = v.x; lp[c*4+1] = v.y; lp[c*4+2] = v.z; lp[c*4+3] = v.w;
            }
            float sk = 0.f;
            float gp[PQN * 3];
#pragma unroll
            for (int pp = 0; pp < PQN; pp++) {
                float lx = lp[pp*3+0], ly = lp[pp*3+1], lz = lp[pp*3+2];
                float gx = R[0]*lx + R[1]*ly + R[2]*lz + tr[0];
                float gy = R[3]*lx + R[4]*ly + R[5]*lz + tr[1];
                float gz = R[6]*lx + R[7]*ly + R[8]*lz + tr[2];
                gp[pp*3+0] = gx; gp[pp*3+1] = gy; gp[pp*3+2] = gz;
                sk += gx*gx + gy*gy + gz*gz;
            }
            g_skP[rp * HH + h] = sk;
            float4* dst = reinterpret_cast<float4*>(g_kpP + ((long)rp * HPQ3 + h * PQN * 3));
#pragma unroll
            for (int c = 0; c < 3; c++)
                dst[c] = make_float4(gp[c*4+0], gp[c*4+1], gp[c*4+2], gp[c*4+3]);
        }
        {
            float lp[PVN * 3];
            const float4* a = reinterpret_cast<const float4*>(g_vp0 + ((long)(b * NN + r0) * HPV3 + h * PVN * 3));
            const float4* bb = reinterpret_cast<const float4*>(g_vp0 + ((long)(b * NN + r1) * HPV3 + h * PVN * 3));
            const float4* cc = reinterpret_cast<const float4*>(g_vp0 + ((long)(b * NN + r2) * HPV3 + h * PVN * 3));
#pragma unroll
            for (int c = 0; c < 6; c++) {
                float4 v = avg3f4(a[c], bb[c], cc[c]);
                lp[c*4+0] = v.x; lp[c*4+1] = v.y; lp[c*4+2] = v.z; lp[c*4+3] = v.w;
            }
            float gp[PVN * 3];
#pragma unroll
            for (int pp = 0; pp < PVN; pp++) {
                float lx = lp[pp*3+0], ly = lp[pp*3+1], lz = lp[pp*3+2];
                gp[pp*3+0] = R[0]*lx + R[1]*ly + R[2]*lz + tr[0];
                gp[pp*3+1] = R[3]*lx + R[4]*ly + R[5]*lz + tr[1];
                gp[pp*3+2] = R[6]*lx + R[7]*ly + R[8]*lz + tr[2];
            }
            float4* dst = reinterpret_cast<float4*>(g_vpP + ((long)rp * HPV3 + h * PVN * 3));
#pragma unroll
            for (int c = 0; c < 6; c++)
                dst[c] = make_float4(gp[c*4+0], gp[c*4+1], gp[c*4+2], gp[c*4+3]);
        }
        return;
    }
    int i4 = i3 - POOLPT;
    if (i4 >= QPT) return;
    int h = i4 % HH;
    int rp = i4 / HH;
    float R[9], tr[3];
#pragma unroll
    for (int r = 0; r < 9; r++) R[r] = g_rP[rp * 9 + r];
#pragma unroll
    for (int r = 0; r < 3; r++) tr[r] = g_tP[rp * 3 + r];
    float lp[PQN * 3];
    float4* qp4 = reinterpret_cast<float4*>(g_qp + ((long)rp * HPQ3 + h * PQN * 3));
#pragma unroll
    for (int c = 0; c < 3; c++) {
        float4 v = qp4[c];
        lp[c*4+0] = v.x; lp[c*4+1] = v.y; lp[c*4+2] = v.z; lp[c*4+3] = v.w;
    }
    float gp[PQN * 3];
#pragma unroll
    for (int p = 0; p < PQN; p++) {
        float lx = lp[p*3+0], ly = lp[p*3+1], lz = lp[p*3+2];
        gp[p*3+0] = R[0]*lx + R[1]*ly + R[2]*lz + tr[0];
        gp[p*3+1] = R[3]*lx + R[4]*ly + R[5]*lz + tr[1];
        gp[p*3+2] = R[6]*lx + R[7]*ly + R[8]*lz + tr[2];
    }
#pragma unroll
    for (int c = 0; c < 3; c++)
        qp4[c] = make_float4(gp[c*4+0], gp[c*4+1], gp[c*4+2], gp[c*4+3]);
}

// ---------------------------------------------------------------------------
// Split-KV attention, extended-key fused logit. TJ=32, ATTS=8,
// __launch_bounds__(64, 8): 128-reg cap => 8 blocks/SM, grid supplies them.
// ---------------------------------------------------------------------------
#define TJ 32
#define ATH 64
__global__ void __launch_bounds__(ATH, 8)
attn_split_kernel(const float* __restrict__ gamma) {
    int bh = blockIdx.x;
    int b = bh / HH, h = bh % HH;
    int i = blockIdx.y * ATH + threadIdx.x;
    int sp = blockIdx.z;
    int tid = threadIdx.x;

    int j_begin = sp * ACHUNK;
    int j_end = j_begin + ACHUNK;
    if (j_end > TT) j_end = TT;

    __shared__ __align__(16) float ke_s[TJ][KED];
    __shared__ __align__(16) float v_s [TJ][CC];
    __shared__ __align__(16) float vg_s[TJ][PVN * 3];

    float gm = gamma[h];
    float gcoef = logf(1.f + __expf(gm)) * WC_HALF;

    int qrow = b * PROW + i;
    u64 qe2[KED / 2];
    {
        const u64* q64 = reinterpret_cast<const u64*>(g_q + (long)qrow * HC + h * CC);
        u64 c1p = pack2(C1, C1);
#pragma unroll
        for (int c = 0; c < CC / 2; c++) { qe2[c] = q64[c]; mul2ip(qe2[c], c1p); }
        const u64* g64 = reinterpret_cast<const u64*>(g_qp + (long)qrow * HPQ3 + h * PQN * 3);
        u64 g2p = pack2(2.f * gcoef, 2.f * gcoef);
#pragma unroll
        for (int c = 0; c < PQN * 3 / 2; c++) { qe2[8 + c] = g64[c]; mul2ip(qe2[8 + c], g2p); }
        qe2[14] = pack2(-gcoef, 0.f);
        qe2[15] = 0ULL;
    }

    float mrun = -1e30f, lrun = 0.f;
    u64 ao2[CC / 2], ag2[PVN * 3 / 2];
#pragma unroll
    for (int c = 0; c < CC / 2; c++) ao2[c] = 0ULL;
#pragma unroll
    for (int x = 0; x < PVN * 3 / 2; x++) ag2[x] = 0ULL;

    for (int j0 = j_begin; j0 < j_end; j0 += TJ) {
        __syncthreads();
        // ke: 8 float4 chunks per key
        for (int x = tid; x < TJ * 8; x += ATH) {
            int j = x >> 3, c4 = x & 7;
            int jj = j0 + j;
            float4 v = make_float4(0.f, 0.f, 0.f, 0.f);
            if (jj < TT) {
                bool raw = (jj < NPAD);
                long rr = raw ? (long)(b * NN + clampsrc(jj)) : (long)(b * PROW + (jj - NPAD));
                if (c4 < 4) {
                    const float* base = raw ? g_k0 : g_kP;
                    v = reinterpret_cast<const float4*>(base + rr * HC + h * CC)[c4];
                } else if (c4 < 7) {
                    const float* base = raw ? g_kpT : g_kpP;
                    v = reinterpret_cast<const float4*>(base + rr * HPQ3 + h * PQN * 3)[c4 - 4];
                } else {
                    const float* base = raw ? g_skR : g_skP;
                    v.x = base[rr * HH + h];
                }
            }
            reinterpret_cast<float4*>(&ke_s[j][0])[c4] = v;
        }
        for (int x = tid; x < TJ * 4; x += ATH) {
            int j = x >> 2, c4 = x & 3;
            int jj = j0 + j;
            float4 v = make_float4(0.f, 0.f, 0.f, 0.f);
            if (jj < TT) {
                bool raw = (jj < NPAD);
                long rr = raw ? (long)(b * NN + clampsrc(jj)) : (long)(b * PROW + (jj - NPAD));
                const float* base = raw ? g_v0 : g_vP;
                v = reinterpret_cast<const float4*>(base + rr * HC + h * CC)[c4];
            }
            reinterpret_cast<float4*>(&v_s[j][0])[c4] = v;
        }
        for (int x = tid; x < TJ * 6; x += ATH) {
            int j = x / 6, c4 = x % 6;
            int jj = j0 + j;
            float4 v = make_float4(0.f, 0.f, 0.f, 0.f);
            if (jj < TT) {
                bool raw = (jj < NPAD);
                long rr = raw ? (long)(b * NN + clampsrc(jj)) : (long)(b * PROW + (jj - NPAD));
                const float* base = raw ? g_vpT : g_vpP;
                v = reinterpret_cast<const float4*>(base + rr * HPV3 + h * PVN * 3)[c4];
            }
            reinterpret_cast<float4*>(&vg_s[j][0])[c4] = v;
        }
        __syncthreads();

        int nv = j_end - j0;
        if (nv > TJ) nv = TJ;

        float logit[TJ];
        float tmax = -1e30f;
#pragma unroll
        for (int jj = 0; jj < TJ; jj++) {
            u64 a1 = 0ULL;
            const ulonglong2* ke128 = reinterpret_cast<const ulonglong2*>(&ke_s[jj][0]);
#pragma unroll
            for (int c = 0; c < KED / 4; c++) {
                ulonglong2 kv = ke128[c];
                fma2(a1, qe2[2*c], kv.x);
                fma2(a1, qe2[2*c+1], kv.y);
            }
            float l1, h1;
            unpack2(a1, l1, h1);
            float lg = l1 + h1;
            logit[jj] = (jj < nv) ? lg : -1e30f;
            tmax = fmaxf(tmax, logit[jj]);
        }
        float mn = fmaxf(mrun, tmax);
        float corr = __expf(mrun - mn);
        lrun *= corr;
        u64 corr2 = pack2(corr, corr);
#pragma unroll
        for (int c = 0; c < CC / 2; c++) mul2ip(ao2[c], corr2);
#pragma unroll
        for (int x = 0; x < PVN * 3 / 2; x++) mul2ip(ag2[x], corr2);
#pragma unroll
        for (int jj = 0; jj < TJ; jj++) {
            float e = __expf(logit[jj] - mn);
            lrun += e;
            u64 ee = pack2(e, e);
            const ulonglong2* v128 = reinterpret_cast<const ulonglong2*>(&v_s[jj][0]);
#pragma unroll
            for (int c = 0; c < CC / 4; c++) {
                ulonglong2 vv = v128[c];
                fma2(ao2[2*c], ee, vv.x);
                fma2(ao2[2*c+1], ee, vv.y);
            }
            const ulonglong2* g128 = reinterpret_cast<const ulonglong2*>(&vg_s[jj][0]);
#pragma unroll
            for (int c = 0; c < PVN * 3 / 4; c++) {
                ulonglong2 vv = g128[c];
                fma2(ag2[2*c], ee, vv.x);
                fma2(ag2[2*c+1], ee, vv.y);
            }
        }
        mrun = mn;
    }

    int p = (qrow * HH + h) * ATTS + sp;
    g_pm[p] = mrun;
    g_pl[p] = lrun;
#pragma unroll
    for (int c = 0; c < CC / 2; c++) {
        float lo, hi; unpack2(ao2[c], lo, hi);
        g_po[(long)p * CC + 2*c] = lo;
        g_po[(long)p * CC + 2*c + 1] = hi;
    }
#pragma unroll
    for (int x = 0; x < PVN * 3 / 2; x++) {
        float lo, hi; unpack2(ag2[x], lo, hi);
        g_pg[(long)p * (PVN * 3) + 2*x] = lo;
        g_pg[(long)p * (PVN * 3) + 2*x + 1] = hi;
    }
}

// ---------------------------------------------------------------------------
// Combine + finalize fused: block handles 16 rows. float4 partial loads.
// ---------------------------------------------------------------------------
#define RPB 16
__global__ void combine_finalize_kernel(const float* __restrict__ bupd,
                                        float* __restrict__ out) {
    __shared__ float soc[RPB][OCW];
    int tid = threadIdx.x;
    int row0 = blockIdx.x * RPB;

    if (tid < RPB * HH) {
        int r = tid / HH;
        int h = tid % HH;
        int row = row0 + r;
        int p0 = (row * HH + h) * ATTS;

        float m = -1e30f;
#pragma unroll
        for (int s = 0; s < ATTS; s++) m = fmaxf(m, g_pm[p0 + s]);
        float L = 0.f;
        float o[CC], g[PVN * 3];
#pragma unroll
        for (int c = 0; c < CC; c++) o[c] = 0.f;
#pragma unroll
        for (int x = 0; x < PVN * 3; x++) g[x] = 0.f;
#pragma unroll
        for (int s = 0; s < ATTS; s++) {
            float w = __expf(g_pm[p0 + s] - m);
            L += g_pl[p0 + s] * w;
            const float4* po4 = reinterpret_cast<const float4*>(g_po + (long)(p0 + s) * CC);
#pragma unroll
            for (int c4 = 0; c4 < CC / 4; c4++) {
                float4 v = po4[c4];
                o[c4*4+0] += w * v.x; o[c4*4+1] += w * v.y;
                o[c4*4+2] += w * v.z; o[c4*4+3] += w * v.w;
            }
            const float4* pg4 = reinterpret_cast<const float4*>(g_pg + (long)(p0 + s) * (PVN * 3));
#pragma unroll
            for (int c4 = 0; c4 < PVN * 3 / 4; c4++) {
                float4 v = pg4[c4];
                g[c4*4+0] += w * v.x; g[c4*4+1] += w * v.y;
                g[c4*4+2] += w * v.z; g[c4*4+3] += w * v.w;
            }
        }
        float inv = 1.f / L;
#pragma unroll
        for (int c = 0; c < CC; c++) o[c] *= inv;
#pragma unroll
        for (int x = 0; x < PVN * 3; x++) g[x] *= inv;

        float R[9], tr[3];
#pragma unroll
        for (int r9 = 0; r9 < 9; r9++) R[r9] = g_rP[row * 9 + r9];
#pragma unroll
        for (int r3 = 0; r3 < 3; r3++) tr[r3] = g_tP[row * 3 + r3];

#pragma unroll
        for (int c = 0; c < CC; c++) soc[r][h * CC + c] = o[c];
#pragma unroll
        for (int pp = 0; pp < PVN; pp++) {
            float gx = g[pp * 3 + 0] - tr[0];
            float gy = g[pp * 3 + 1] - tr[1];
            float gz = g[pp * 3 + 2] - tr[2];
            float lx = R[0] * gx + R[3] * gy + R[6] * gz;
            float ly = R[1] * gx + R[4] * gy + R[7] * gz;
            float lz = R[2] * gx + R[5] * gy + R[8] * gz;
            soc[r][HC + h * PVN * 3 + pp * 3 + 0] = lx;
            soc[r][HC + h * PVN * 3 + pp * 3 + 1] = ly;
            soc[r][HC + h * PVN * 3 + pp * 3 + 2] = lz;
            soc[r][HC + HPV3 + h * PVN + pp] =
                sqrtf(lx * lx + ly * ly + lz * lz + 1e-8f);
        }
    }
    __syncthreads();

    int warp = tid >> 5;
    int lane = tid & 31;
    int row = row0 + warp;

    float acc[6] = {0.f, 0.f, 0.f, 0.f, 0.f, 0.f};
    for (int k = lane; k < OCW; k += 32) {
        float v = soc[warp][k];
#pragma unroll
        for (int j = 0; j < 6; j++) acc[j] += v * g_wfold[j * OCW + k];
    }
#pragma unroll
    for (int off = 16; off > 0; off >>= 1)
#pragma unroll
        for (int j = 0; j < 6; j++)
            acc[j] += __shfl_down_sync(0xffffffffu, acc[j], off);
    if (lane != 0) return;

    float u[6];
#pragma unroll
    for (int j = 0; j < 6; j++) u[j] = acc[j] + bupd[j];

    float bq = u[0], cq = u[1], dq = u[2];
    float ninv = rsqrtf(1.f + bq * bq + cq * cq + dq * dq);
    float w = ninv, x = bq * ninv, y = cq * ninv, z = dq * ninv;
    float Ru[9];
    Ru[0] = 1.f - 2.f * (y * y + z * z); Ru[1] = 2.f * (x * y - w * z); Ru[2] = 2.f * (x * z + w * y);
    Ru[3] = 2.f * (x * y + w * z); Ru[4] = 1.f - 2.f * (x * x + z * z); Ru[5] = 2.f * (y * z - w * x);
    Ru[6] = 2.f * (x * z - w * y); Ru[7] = 2.f * (y * z + w * x); Ru[8] = 1.f - 2.f * (x * x + y * y);

    float R[9];
#pragma unroll
    for (int r = 0; r < 9; r++) R[r] = g_rP[row * 9 + r];

    float Rn[9];
#pragma unroll
    for (int r = 0; r < 3; r++)
#pragma unroll
        for (int c = 0; c < 3; c++) {
            float a = 0.f;
#pragma unroll
            for (int k = 0; k < 3; k++) a += R[r * 3 + k] * Ru[k * 3 + c];
            Rn[r * 3 + c] = a;
        }

    out[row * 3 + 0] = R[0] * u[3] + R[1] * u[4] + R[2] * u[5] + g_tP[row * 3 + 0];
    out[row * 3 + 1] = R[3] * u[3] + R[4] * u[4] + R[5] * u[5] + g_tP[row * 3 + 1];
    out[row * 3 + 2] = R[6] * u[3] + R[7] * u[4] + R[8] * u[5] + g_tP[row * 3 + 2];
    float* rout = out + BB * PROW * 3;
#pragma unroll
    for (int r = 0; r < 9; r++) rout[row * 9 + r] = Rn[r];
}

// ---------------------------------------------------------------------------
extern "C" void kernel_launch(void* const* d_in, const int* in_sizes, int n_in,
                              void* d_out, int out_size) {
    const float* trans = (const float*)d_in[0];
    const float* rots  = (const float*)d_in[1];
    const float* s     = (const float*)d_in[2];
    const float* wq    = (const float*)d_in[3];
    const float* wk    = (const float*)d_in[4];
    const float* wv    = (const float*)d_in[5];
    const float* wqp   = (const float*)d_in[6];
    const float* wkp   = (const float*)d_in[7];
    const float* wvp   = (const float*)d_in[8];
    const float* gamma = (const float*)d_in[9];
    const float* wout  = (const float*)d_in[10];
    const float* wupd  = (const float*)d_in[11];
    const float* bupd  = (const float*)d_in[12];
    float* out = (float*)d_out;

    float *p_s_pool, *p_k0, *p_v0, *p_kp0, *p_vp0, *p_q, *p_qp;
    cudaGetSymbolAddress((void**)&p_s_pool, g_s_pool);
    cudaGetSymbolAddress((void**)&p_k0, g_k0);
    cudaGetSymbolAddress((void**)&p_v0, g_v0);
    cudaGetSymbolAddress((void**)&p_kp0, g_kp0);
    cudaGetSymbolAddress((void**)&p_vp0, g_vp0);
    cudaGetSymbolAddress((void**)&p_q, g_q);
    cudaGetSymbolAddress((void**)&p_qp, g_qp);

    // 1. prep + weight fold (fused)
    prep_fold_kernel<<<(SP_TOT + TRP_TOT + FOLD_TOT + 255) / 256, 256>>>(
        s, trans, rots, wout, wupd);

    // 2. projection GEMMs (tf32 tensor cores)
    TaskPack P;
    int Mraw = BB * NN;
    int Mpool = BB * PROW;
    auto setTask = [&](int ti, const float* A, const float* B, float* C,
                       int M, int N, int K) {
        P.t[ti].A = A; P.t[ti].B = B; P.t[ti].C = C;
        P.t[ti].M = M; P.t[ti].N = N; P.t[ti].K = K;
        P.t[ti].gx = (N + GBN - 1) / GBN;
    };
    setTask(0, s, wk,  p_k0,  Mraw, HC,   CSD);
    setTask(1, s, wv,  p_v0,  Mraw, HC,   CSD);
    setTask(2, s, wkp, p_kp0, Mraw, HPQ3, CSD);
    setTask(3, s, wvp, p_vp0, Mraw, HPV3, CSD);
    setTask(4, p_s_pool, wq,  p_q,  Mpool, HC,   CSD);
    setTask(5, p_s_pool, wqp, p_qp, Mpool, HPQ3, CSD);
    P.ofs[0] = 0;
    for (int ti = 0; ti < NTASK; ti++) {
        int gy = (P.t[ti].M + GBM - 1) / GBM;
        P.ofs[ti + 1] = P.ofs[ti] + P.t[ti].gx * gy;
    }
    mgemm_kernel<<<P.ofs[NTASK], 256>>>(P);

    // 3. transforms
    transform_kernel<<<(XF_TOT + 255) / 256, 256>>>(trans, rots);

    // 4. split-KV attention (ATTS=8 supply + 128-reg cap = 16 warps/SM)
    attn_split_kernel<<<dim3(BB * HH, PROW / ATH, ATTS), ATH>>>(gamma);

    // 5. combine + finalize (fused, float4 partial loads)
    combine_finalize_kernel<<<(BB * PROW) / RPB, RPB * 32>>>(bupd, out);
}

// round 15
// speedup vs baseline: 1.7615x; 1.7615x over previous
#include <cuda_runtime.h>
#include <math.h>

// Problem constants
#define BB 2
#define NN 1024
#define CSD 384
#define HH 12
#define CC 16
#define PQN 4
#define PVN 8
#define NPAD 1026        // N + 2*PAD
#define PROW 512         // num_pool
#define TT 1538          // NPAD + PROW
#define HC 192           // H*C
#define HPQ3 144         // H*PQ*3
#define HPV3 288         // H*PV*3
#define OCW 576          // HC + HPV3 + H*PV
#define ATTS 4           // split-KV factor
#define ACHUNK ((TT + ATTS - 1) / ATTS)   // 385
#define KED 32           // extended key dim (16 k + 12 kg + 4 pad)
#define VED 40           // extended value dim (16 v + 24 vg)
#define TJ 32            // keys per tile

#define C1 0.176776695f       // w_l * (1/sqrt(C))
#define WC_HALF 0.117851130f  // w_c/2

typedef unsigned long long u64;

__device__ __forceinline__ unsigned f2tf32(float v) {
    unsigned r; asm("cvt.rna.tf32.f32 %0, %1;" : "=r"(r) : "f"(v)); return r;
}
__device__ __forceinline__ void mma_tf32(float* d, unsigned a0, unsigned a1,
                                         unsigned a2, unsigned a3,
                                         unsigned b0, unsigned b1) {
    asm volatile(
        "mma.sync.aligned.m16n8k8.row.col.f32.tf32.tf32.f32 "
        "{%0,%1,%2,%3}, {%4,%5,%6,%7}, {%8,%9}, {%0,%1,%2,%3};"
        : "+f"(d[0]), "+f"(d[1]), "+f"(d[2]), "+f"(d[3])
        : "r"(a0), "r"(a1), "r"(a2), "r"(a3), "r"(b0), "r"(b1));
}

// Scratch (device globals)
__device__ float g_s_pool[BB*PROW*CSD];
__device__ float g_tP[BB*PROW*3];
__device__ float g_rP[BB*PROW*9];
__device__ float g_k0 [BB*NN*HC];
__device__ float g_v0 [BB*NN*HC];
__device__ float g_kp0[BB*NN*HPQ3];
__device__ float g_vp0[BB*NN*HPV3];
__device__ float g_kpT[BB*NN*HPQ3];
__device__ float g_vpT[BB*NN*HPV3];
__device__ float g_skR[BB*NN*HH];
__device__ float g_kP [BB*PROW*HC];
__device__ float g_vP [BB*PROW*HC];
__device__ float g_kpP[BB*PROW*HPQ3];
__device__ float g_vpP[BB*PROW*HPV3];
__device__ float g_skP[BB*PROW*HH];
__device__ float g_q  [BB*PROW*HC];
__device__ float g_qp [BB*PROW*HPQ3];
__device__ float g_wfold[6*OCW];

#define NPART (BB*PROW*HH*ATTS)
__device__ float g_pm[NPART];
__device__ float g_pl[NPART];
__device__ float g_po[NPART*CC];
__device__ float g_pg[NPART*PVN*3];

__device__ __forceinline__ int clampsrc(int e) {
    int v = e - 1;
    return v < 0 ? 0 : (v > NN - 1 ? NN - 1 : v);
}

// ---------------------------------------------------------------------------
// Prep + weight fold fused
// ---------------------------------------------------------------------------
#define SP_TOT (BB*PROW*CSD)
#define TRP_TOT (BB*PROW*12)
#define FOLD_TOT (OCW*32)
__global__ void prep_fold_kernel(const float* __restrict__ s,
                                 const float* __restrict__ trans,
                                 const float* __restrict__ rots,
                                 const float* __restrict__ wout,
                                 const float* __restrict__ wupd) {
    int idx = blockIdx.x * blockDim.x + threadIdx.x;
    if (idx < SP_TOT) {
        int c = idx % CSD;
        int bp = idx / CSD;
        int p = bp % PROW;
        int b = bp / PROW;
        g_s_pool[idx] = (s[(b * NN + clampsrc(2 * p    )) * CSD + c]
                       + s[(b * NN + clampsrc(2 * p + 1)) * CSD + c]
                       + s[(b * NN + clampsrc(2 * p + 2)) * CSD + c]) * (1.f / 3.f);
        return;
    }
    int k = idx - SP_TOT;
    if (k < TRP_TOT) {
        int d = k % 12;
        int bp = k / 12;
        int p = bp % PROW;
        int b = bp / PROW;
        int r0 = clampsrc(2 * p), r1 = clampsrc(2 * p + 1), r2 = clampsrc(2 * p + 2);
        if (d < 3) {
            g_tP[bp * 3 + d] = (trans[(b * NN + r0) * 3 + d]
                              + trans[(b * NN + r1) * 3 + d]
                              + trans[(b * NN + r2) * 3 + d]) * (1.f / 3.f);
        } else {
            int r = d - 3;
            g_rP[bp * 9 + r] = (rots[(b * NN + r0) * 9 + r]
                              + rots[(b * NN + r1) * 9 + r]
                              + rots[(b * NN + r2) * 9 + r]) * (1.f / 3.f);
        }
        return;
    }
    int fi = k - TRP_TOT;
    if (fi >= FOLD_TOT) return;
    int gw = fi >> 5;
    int lane = fi & 31;
    const float* wr = wout + (long)gw * CSD;
    float acc[6] = {0, 0, 0, 0, 0, 0};
    for (int m = lane; m < CSD; m += 32) {
        float w = wr[m];
#pragma unroll
        for (int j = 0; j < 6; j++) acc[j] += w * __ldg(&wupd[m * 6 + j]);
    }
#pragma unroll
    for (int off = 16; off > 0; off >>= 1)
#pragma unroll
        for (int j = 0; j < 6; j++)
            acc[j] += __shfl_down_sync(0xffffffffu, acc[j], off);
    if (lane == 0) {
#pragma unroll
        for (int j = 0; j < 6; j++) g_wfold[j * OCW + gw] = acc[j];
    }
}

// ---------------------------------------------------------------------------
// Fused multi-task GEMM on tensor cores (tf32 mma m16n8k8) — proven.
// ---------------------------------------------------------------------------
#define NTASK 6
struct GemmTask {
    const float* A;
    const float* B;
    float* C;
    int M, N, K, gx;
};
struct TaskPack {
    GemmTask t[NTASK];
    int ofs[NTASK + 1];
};

#define GBM 64
#define GBN 64
#define GBK 16
__global__ void mgemm_kernel(TaskPack P) {
    int bid = blockIdx.x;
    int ti = 0;
#pragma unroll
    for (int x = 0; x < NTASK - 1; x++)
        if (bid >= P.ofs[x + 1]) ti = x + 1;
    GemmTask tk = P.t[ti];
    int lb = bid - P.ofs[ti];
    int bx = lb % tk.gx, by = lb / tk.gx;

    __shared__ unsigned As[GBM][GBK + 1];
    __shared__ unsigned Bs[GBK][GBN + 8];

    int tid = threadIdx.x;
    int warp = tid >> 5, lane = tid & 31;
    int gid = lane >> 2, tig = lane & 3;
    int wm = warp & 3;
    int wn = warp >> 2;
    int row0 = by * GBM;
    int col0 = bx * GBN;
    const float* A = tk.A;
    const float* Bm = tk.B;
    int M = tk.M, Nn = tk.N, K = tk.K;

    float d[4][4];
#pragma unroll
    for (int t = 0; t < 4; t++)
#pragma unroll
        for (int c = 0; c < 4; c++) d[t][c] = 0.f;

    for (int k0 = 0; k0 < K; k0 += GBK) {
#pragma unroll
        for (int x = 0; x < 4; x++) {
            int li = tid + x * 256;
            int m = li >> 4, kk = li & 15;
            int gm = row0 + m;
            float v = (gm < M) ? A[(long)gm * K + k0 + kk] : 0.f;
            As[m][kk] = f2tf32(v);
        }
#pragma unroll
        for (int x = 0; x < 4; x++) {
            int li = tid + x * 256;
            int kk = li >> 6, n = li & 63;
            int gn = col0 + n;
            float v = (gn < Nn) ? Bm[(long)(k0 + kk) * Nn + gn] : 0.f;
            Bs[kk][n] = f2tf32(v);
        }
        __syncthreads();

#pragma unroll
        for (int ks = 0; ks < 2; ks++) {
            int kb = ks * 8;
            int ra = wm * 16 + gid;
            unsigned a0 = As[ra][kb + tig];
            unsigned a1 = As[ra + 8][kb + tig];
            unsigned a2 = As[ra][kb + tig + 4];
            unsigned a3 = As[ra + 8][kb + tig + 4];
#pragma unroll
            for (int t = 0; t < 4; t++) {
                int nb = wn * 32 + t * 8;
                unsigned b0 = Bs[kb + tig][nb + gid];
                unsigned b1 = Bs[kb + tig + 4][nb + gid];
                mma_tf32(d[t], a0, a1, a2, a3, b0, b1);
            }
        }
        __syncthreads();
    }

#pragma unroll
    for (int t = 0; t < 4; t++) {
        int gn0 = col0 + wn * 32 + t * 8 + tig * 2;
        int gm0 = row0 + wm * 16 + gid;
        if (gm0 < M) {
            if (gn0 < Nn)     tk.C[(long)gm0 * Nn + gn0]     = d[t][0];
            if (gn0 + 1 < Nn) tk.C[(long)gm0 * Nn + gn0 + 1] = d[t][1];
        }
        int gm1 = gm0 + 8;
        if (gm1 < M) {
            if (gn0 < Nn)     tk.C[(long)gm1 * Nn + gn0]     = d[t][2];
            if (gn0 + 1 < Nn) tk.C[(long)gm1 * Nn + gn0 + 1] = d[t][3];
        }
    }
}

// ---------------------------------------------------------------------------
// Transform kernel (proven), 4 ranges.
// ---------------------------------------------------------------------------
#define RAWPT (BB*NN*HH)
#define POOLKV (BB*PROW*(HC/4)*2)
#define POOLPT (BB*PROW*HH)
#define QPT (BB*PROW*HH)
#define XF_TOT (RAWPT + POOLKV + POOLPT + QPT)

__device__ __forceinline__ float4 avg3f4(float4 a, float4 b, float4 c) {
    return make_float4((a.x + b.x + c.x) * (1.f / 3.f),
                       (a.y + b.y + c.y) * (1.f / 3.f),
                       (a.z + b.z + c.z) * (1.f / 3.f),
                       (a.w + b.w + c.w) * (1.f / 3.f));
}

__global__ void transform_kernel(const float* __restrict__ trans,
                                 const float* __restrict__ rots) {
    int idx = blockIdx.x * blockDim.x + threadIdx.x;
    if (idx < RAWPT) {
        int h = idx % HH;
        int rn = idx / HH;
        float R[9], tr[3];
#pragma unroll
        for (int r = 0; r < 9; r++) R[r] = rots[rn * 9 + r];
#pragma unroll
        for (int r = 0; r < 3; r++) tr[r] = trans[rn * 3 + r];

        {
            const float4* src = reinterpret_cast<const float4*>(g_kp0 + ((long)rn * HPQ3 + h * PQN * 3));
            float lp[PQN * 3];
#pragma unroll
            for (int c = 0; c < 3; c++) {
                float4 v = src[c];
                lp[c*4+0] = v.x; lp[c*4+1] = v.y; lp[c*4+2] = v.z; lp[c*4+3] = v.w;
            }
            float sk = 0.f;
            float gp[PQN * 3];
#pragma unroll
            for (int p = 0; p < PQN; p++) {
                float lx = lp[p*3+0], ly = lp[p*3+1], lz = lp[p*3+2];
                float gx = R[0]*lx + R[1]*ly + R[2]*lz + tr[0];
                float gy = R[3]*lx + R[4]*ly + R[5]*lz + tr[1];
                float gz = R[6]*lx + R[7]*ly + R[8]*lz + tr[2];
                gp[p*3+0] = gx; gp[p*3+1] = gy; gp[p*3+2] = gz;
                sk += gx*gx + gy*gy + gz*gz;
            }
            g_skR[rn * HH + h] = sk;
            float4* dst = reinterpret_cast<float4*>(g_kpT + ((long)rn * HPQ3 + h * PQN * 3));
#pragma unroll
            for (int c = 0; c < 3; c++)
                dst[c] = make_float4(gp[c*4+0], gp[c*4+1], gp[c*4+2], gp[c*4+3]);
        }
        {
            const float4* src = reinterpret_cast<const float4*>(g_vp0 + ((long)rn * HPV3 + h * PVN * 3));
            float lp[PVN * 3];
#pragma unroll
            for (int c = 0; c < 6; c++) {
                float4 v = src[c];
                lp[c*4+0] = v.x; lp[c*4+1] = v.y; lp[c*4+2] = v.z; lp[c*4+3] = v.w;
            }
            float gp[PVN * 3];
#pragma unroll
            for (int p = 0; p < PVN; p++) {
                float lx = lp[p*3+0], ly = lp[p*3+1], lz = lp[p*3+2];
                gp[p*3+0] = R[0]*lx + R[1]*ly + R[2]*lz + tr[0];
                gp[p*3+1] = R[3]*lx + R[4]*ly + R[5]*lz + tr[1];
                gp[p*3+2] = R[6]*lx + R[7]*ly + R[8]*lz + tr[2];
            }
            float4* dst = reinterpret_cast<float4*>(g_vpT + ((long)rn * HPV3 + h * PVN * 3));
#pragma unroll
            for (int c = 0; c < 6; c++)
                dst[c] = make_float4(gp[c*4+0], gp[c*4+1], gp[c*4+2], gp[c*4+3]);
        }
        return;
    }
    int i2 = idx - RAWPT;
    if (i2 < POOLKV) {
        int c = i2 % (HC / 4);
        int rest = i2 / (HC / 4);
        int rp = rest % (BB * PROW);
        int sel = rest / (BB * PROW);
        int p = rp % PROW;
        int b = rp / PROW;
        int r0 = clampsrc(2 * p), r1 = clampsrc(2 * p + 1), r2 = clampsrc(2 * p + 2);
        const float* srcbase = sel ? g_v0 : g_k0;
        float* dstbase = sel ? g_vP : g_kP;
        float4 a = reinterpret_cast<const float4*>(srcbase + ((long)(b * NN + r0) * HC))[c];
        float4 bb = reinterpret_cast<const float4*>(srcbase + ((long)(b * NN + r1) * HC))[c];
        float4 cc = reinterpret_cast<const float4*>(srcbase + ((long)(b * NN + r2) * HC))[c];
        reinterpret_cast<float4*>(dstbase + ((long)rp * HC))[c] = avg3f4(a, bb, cc);
        return;
    }
    int i3 = i2 - POOLKV;
    if (i3 < POOLPT) {
        int h = i3 % HH;
        int rp = i3 / HH;
        int p = rp % PROW;
        int b = rp / PROW;
        int r0 = clampsrc(2 * p), r1 = clampsrc(2 * p + 1), r2 = clampsrc(2 * p + 2);
        float R[9], tr[3];
#pragma unroll
        for (int r = 0; r < 9; r++) R[r] = g_rP[rp * 9 + r];
#pragma unroll
        for (int r = 0; r < 3; r++) tr[r] = g_tP[rp * 3 + r];

        {
            float lp[PQN * 3];
            const float4* a = reinterpret_cast<const float4*>(g_kp0 + ((long)(b * NN + r0) * HPQ3 + h * PQN * 3));
            const float4* bb = reinterpret_cast<const float4*>(g_kp0 + ((long)(b * NN + r1) * HPQ3 + h * PQN * 3));
            const float4* cc = reinterpret_cast<const float4*>(g_kp0 + ((long)(b * NN + r2) * HPQ3 + h * PQN * 3));
#pragma unroll
            for (int c = 0; c < 3; c++) {
                float4 v = avg3f4(a[c], bb[c], cc[c]);
                lp[c*4+0] = v.x; lp[c*4+1] = v.y; lp[c*4+2] = v.z; lp[c*4+3] = v.w;
            }
            float sk = 0.f;
            float gp[PQN * 3];
#pragma unroll
            for (int pp = 0; pp < PQN; pp++) {
                float lx = lp[pp*3+0], ly = lp[pp*3+1], lz = lp[pp*3+2];
                float gx = R[0]*lx + R[1]*ly + R[2]*lz + tr[0];
                float gy = R[3]*lx + R[4]*ly + R[5]*lz + tr[1];
                float gz = R[6]*lx + R[7]*ly + R[8]*lz + tr[2];
                gp[pp*3+0] = gx; gp[pp*3+1] = gy; gp[pp*3+2] = gz;
                sk += gx*gx + gy*gy + gz*gz;
            }
            g_skP[rp * HH + h] = sk;
            float4* dst = reinterpret_cast<float4*>(g_kpP + ((long)rp * HPQ3 + h * PQN * 3));
#pragma unroll
            for (int c = 0; c < 3; c++)
                dst[c] = make_float4(gp[c*4+0], gp[c*4+1], gp[c*4+2], gp[c*4+3]);
        }
        {
            float lp[PVN * 3];
            const float4* a = reinterpret_cast<const float4*>(g_vp0 + ((long)(b * NN + r0) * HPV3 + h * PVN * 3));
            const float4* bb = reinterpret_cast<const float4*>(g_vp0 + ((long)(b * NN + r1) * HPV3 + h * PVN * 3));
            const float4* cc = reinterpret_cast<const float4*>(g_vp0 + ((long)(b * NN + r2) * HPV3 + h * PVN * 3));
#pragma unroll
            for (int c = 0; c < 6; c++) {
                float4 v = avg3f4(a[c], bb[c], cc[c]);
                lp[c*4+0] = v.x; lp[c*4+1] = v.y; lp[c*4+2] = v.z; lp[c*4+3] = v.w;
            }
            float gp[PVN * 3];
#pragma unroll
            for (int pp = 0; pp < PVN; pp++) {
                float lx = lp[pp*3+0], ly = lp[pp*3+1], lz = lp[pp*3+2];
                gp[pp*3+0] = R[0]*lx + R[1]*ly + R[2]*lz + tr[0];
                gp[pp*3+1] = R[3]*lx + R[4]*ly + R[5]*lz + tr[1];
                gp[pp*3+2] = R[6]*lx + R[7]*ly + R[8]*lz + tr[2];
            }
            float4* dst = reinterpret_cast<float4*>(g_vpP + ((long)rp * HPV3 + h * PVN * 3));
#pragma unroll
            for (int c = 0; c < 6; c++)
                dst[c] = make_float4(gp[c*4+0], gp[c*4+1], gp[c*4+2], gp[c*4+3]);
        }
        return;
    }
    int i4 = i3 - POOLPT;
    if (i4 >= QPT) return;
    int h = i4 % HH;
    int rp = i4 / HH;
    float R[9], tr[3];
#pragma unroll
    for (int r = 0; r < 9; r++) R[r] = g_rP[rp * 9 + r];
#pragma unroll
    for (int r = 0; r < 3; r++) tr[r] = g_tP[rp * 3 + r];
    float lp[PQN * 3];
    float4* qp4 = reinterpret_cast<float4*>(g_qp + ((long)rp * HPQ3 + h * PQN * 3));
#pragma unroll
    for (int c = 0; c < 3; c++) {
        float4 v = qp4[c];
        lp[c*4+0] = v.x; lp[c*4+1] = v.y; lp[c*4+2] = v.z; lp[c*4+3] = v.w;
    }
    float gp[PQN * 3];
#pragma unroll
    for (int p = 0; p < PQN; p++) {
        float lx = lp[p*3+0], ly = lp[p*3+1], lz = lp[p*3+2];
        gp[p*3+0] = R[0]*lx + R[1]*ly + R[2]*lz + tr[0];
        gp[p*3+1] = R[3]*lx + R[4]*ly + R[5]*lz + tr[1];
        gp[p*3+2] = R[6]*lx + R[7]*ly + R[8]*lz + tr[2];
    }
#pragma unroll
    for (int c = 0; c < 3; c++)
        qp4[c] = make_float4(gp[c*4+0], gp[c*4+1], gp[c*4+2], gp[c*4+3]);
}

// ---------------------------------------------------------------------------
// Tensor-core flash attention. Block = 128 threads = 4 warps, 16 queries/warp.
// grid (B*H, PROW/64, ATTS). S = QE x KE^T via m16n8k8 tf32; softmax on
// fragments; P -> smem -> PV mma. sk term added fp32-scalar post-mma.
// Partials written to g_pm/pl/po/pg (proven combine path).
// ---------------------------------------------------------------------------
__global__ void attn_mma_kernel(const float* __restrict__ gamma) {
    __shared__ unsigned qe_s[4][16][36];
    __shared__ unsigned ke_s[TJ][36];
    __shared__ unsigned ve_s[TJ][44];
    __shared__ unsigned p_s[4][16][36];
    __shared__ float sk_s[TJ];

    int bh = blockIdx.x;
    int b = bh / HH, h = bh % HH;
    int sp = blockIdx.z;
    int tid = threadIdx.x;
    int warp = tid >> 5, lane = tid & 31;
    int gid = lane >> 2, tig = lane & 3;

    int j_begin = sp * ACHUNK;
    int j_end = j_begin + ACHUNK;
    if (j_end > TT) j_end = TT;

    float gm = gamma[h];
    float gco = logf(1.f + __expf(gm)) * WC_HALF;

    int qbase = blockIdx.y * 64 + warp * 16;   // pooled row base for this warp

    // Build QE (16 x 32): [C1*q | 2g*qp | 0 0 0 0]
    for (int idx = lane; idx < 16 * 32; idx += 32) {
        int r = idx >> 5, c = idx & 31;
        long qrow = (long)(b * PROW + qbase + r);
        float v = 0.f;
        if (c < 16) v = C1 * g_q[qrow * HC + h * CC + c];
        else if (c < 28) v = 2.f * gco * g_qp[qrow * HPQ3 + h * 12 + (c - 16)];
        qe_s[warp][r][c] = f2tf32(v);
    }
    __syncwarp();

    float S[4][4];
    float O[5][4];
#pragma unroll
    for (int n = 0; n < 5; n++)
#pragma unroll
        for (int c = 0; c < 4; c++) O[n][c] = 0.f;
    float m_lo = -1e30f, m_hi = -1e30f, l_lo = 0.f, l_hi = 0.f;

    for (int j0 = j_begin; j0 < j_end; j0 += TJ) {
        __syncthreads();
        // KE tile: 32 keys x 8 uint4 chunks (chunk 7 = zeros; sk separate)
        for (int x = tid; x < TJ * 8; x += 128) {
            int j = x >> 3, c4 = x & 7;
            int jj = j0 + j;
            float4 v = make_float4(0.f, 0.f, 0.f, 0.f);
            if (jj < j_end && c4 < 7) {
                bool raw = (jj < NPAD);
                long rr = raw ? (long)(b * NN + clampsrc(jj)) : (long)(b * PROW + (jj - NPAD));
                if (c4 < 4) {
                    const float* base = raw ? g_k0 : g_kP;
                    v = reinterpret_cast<const float4*>(base + rr * HC + h * CC)[c4];
                } else {
                    const float* base = raw ? g_kpT : g_kpP;
                    v = reinterpret_cast<const float4*>(base + rr * HPQ3 + h * 12)[c4 - 4];
                }
            }
            uint4 u;
            u.x = f2tf32(v.x); u.y = f2tf32(v.y); u.z = f2tf32(v.z); u.w = f2tf32(v.w);
            *reinterpret_cast<uint4*>(&ke_s[j][c4 * 4]) = u;
        }
        // VE tile: 32 keys x 10 chunks (v 0..3, vg 4..9)
        for (int x = tid; x < TJ * 10; x += 128) {
            int j = x / 10, c4 = x % 10;
            int jj = j0 + j;
            float4 v = make_float4(0.f, 0.f, 0.f, 0.f);
            if (jj < j_end) {
                bool raw = (jj < NPAD);
                long rr = raw ? (long)(b * NN + clampsrc(jj)) : (long)(b * PROW + (jj - NPAD));
                if (c4 < 4) {
                    const float* base = raw ? g_v0 : g_vP;
                    v = reinterpret_cast<const float4*>(base + rr * HC + h * CC)[c4];
                } else {
                    const float* base = raw ? g_vpT : g_vpP;
                    v = reinterpret_cast<const float4*>(base + rr * HPV3 + h * 24)[c4 - 4];
                }
            }
            uint4 u;
            u.x = f2tf32(v.x); u.y = f2tf32(v.y); u.z = f2tf32(v.z); u.w = f2tf32(v.w);
            *reinterpret_cast<uint4*>(&ve_s[j][c4 * 4]) = u;
        }
        // sk (fp32, exact)
        for (int x = tid; x < TJ; x += 128) {
            int jj = j0 + x;
            float v = 0.f;
            if (jj < j_end) {
                bool raw = (jj < NPAD);
                long rr = raw ? (long)(b * NN + clampsrc(jj)) : (long)(b * PROW + (jj - NPAD));
                v = raw ? g_skR[rr * HH + h] : g_skP[rr * HH + h];
            }
            sk_s[x] = v;
        }
        __syncthreads();

        // S = QE x KE^T  (4 key groups of 8, 4 k-steps of 8)
#pragma unroll
        for (int g4 = 0; g4 < 4; g4++)
            S[g4][0] = S[g4][1] = S[g4][2] = S[g4][3] = 0.f;
#pragma unroll
        for (int ks = 0; ks < 4; ks++) {
            unsigned a0 = qe_s[warp][gid][ks * 8 + tig];
            unsigned a1 = qe_s[warp][gid + 8][ks * 8 + tig];
            unsigned a2 = qe_s[warp][gid][ks * 8 + tig + 4];
            unsigned a3 = qe_s[warp][gid + 8][ks * 8 + tig + 4];
#pragma unroll
            for (int g4 = 0; g4 < 4; g4++) {
                unsigned b0 = ke_s[g4 * 8 + gid][ks * 8 + tig];
                unsigned b1 = ke_s[g4 * 8 + gid][ks * 8 + tig + 4];
                mma_tf32(S[g4], a0, a1, a2, a3, b0, b1);
            }
        }

        // add -g*sk (fp32), mask invalid columns
        float mloc_lo = -1e30f, mloc_hi = -1e30f;
#pragma unroll
        for (int g4 = 0; g4 < 4; g4++) {
            int c0 = j0 + g4 * 8 + 2 * tig;
            float nsk0 = -gco * sk_s[g4 * 8 + 2 * tig];
            float nsk1 = -gco * sk_s[g4 * 8 + 2 * tig + 1];
            S[g4][0] += nsk0; S[g4][1] += nsk1;
            S[g4][2] += nsk0; S[g4][3] += nsk1;
            if (c0 >= j_end)     { S[g4][0] = -1e30f; S[g4][2] = -1e30f; }
            if (c0 + 1 >= j_end) { S[g4][1] = -1e30f; S[g4][3] = -1e30f; }
            mloc_lo = fmaxf(mloc_lo, fmaxf(S[g4][0], S[g4][1]));
            mloc_hi = fmaxf(mloc_hi, fmaxf(S[g4][2], S[g4][3]));
        }
        mloc_lo = fmaxf(mloc_lo, __shfl_xor_sync(0xffffffffu, mloc_lo, 1));
        mloc_lo = fmaxf(mloc_lo, __shfl_xor_sync(0xffffffffu, mloc_lo, 2));
        mloc_hi = fmaxf(mloc_hi, __shfl_xor_sync(0xffffffffu, mloc_hi, 1));
        mloc_hi = fmaxf(mloc_hi, __shfl_xor_sync(0xffffffffu, mloc_hi, 2));

        float mn_lo = fmaxf(m_lo, mloc_lo);
        float mn_hi = fmaxf(m_hi, mloc_hi);
        float corr_lo = __expf(m_lo - mn_lo);
        float corr_hi = __expf(m_hi - mn_hi);
        m_lo = mn_lo; m_hi = mn_hi;

        float es_lo = 0.f, es_hi = 0.f;
#pragma unroll
        for (int g4 = 0; g4 < 4; g4++) {
            float e0 = __expf(S[g4][0] - m_lo);
            float e1 = __expf(S[g4][1] - m_lo);
            float e2 = __expf(S[g4][2] - m_hi);
            float e3 = __expf(S[g4][3] - m_hi);
            es_lo += e0 + e1;
            es_hi += e2 + e3;
            p_s[warp][gid][g4 * 8 + 2 * tig]         = f2tf32(e0);
            p_s[warp][gid][g4 * 8 + 2 * tig + 1]     = f2tf32(e1);
            p_s[warp][gid + 8][g4 * 8 + 2 * tig]     = f2tf32(e2);
            p_s[warp][gid + 8][g4 * 8 + 2 * tig + 1] = f2tf32(e3);
        }
        es_lo += __shfl_xor_sync(0xffffffffu, es_lo, 1);
        es_lo += __shfl_xor_sync(0xffffffffu, es_lo, 2);
        es_hi += __shfl_xor_sync(0xffffffffu, es_hi, 1);
        es_hi += __shfl_xor_sync(0xffffffffu, es_hi, 2);
        l_lo = l_lo * corr_lo + es_lo;
        l_hi = l_hi * corr_hi + es_hi;

#pragma unroll
        for (int ng = 0; ng < 5; ng++) {
            O[ng][0] *= corr_lo; O[ng][1] *= corr_lo;
            O[ng][2] *= corr_hi; O[ng][3] *= corr_hi;
        }
        __syncwarp();

        // O += P x VE  (5 dim-groups of 8, 4 k-steps of 8 keys)
#pragma unroll
        for (int ks = 0; ks < 4; ks++) {
            unsigned a0 = p_s[warp][gid][ks * 8 + tig];
            unsigned a1 = p_s[warp][gid + 8][ks * 8 + tig];
            unsigned a2 = p_s[warp][gid][ks * 8 + tig + 4];
            unsigned a3 = p_s[warp][gid + 8][ks * 8 + tig + 4];
#pragma unroll
            for (int ng = 0; ng < 5; ng++) {
                unsigned b0 = ve_s[ks * 8 + tig][ng * 8 + gid];
                unsigned b1 = ve_s[ks * 8 + tig + 4][ng * 8 + gid];
                mma_tf32(O[ng], a0, a1, a2, a3, b0, b1);
            }
        }
    }

    // write partials
    long qrow_lo = (long)(b * PROW + qbase + gid);
    long qrow_hi = qrow_lo + 8;
    long p_lo = (qrow_lo * HH + h) * ATTS + sp;
    long p_hi = (qrow_hi * HH + h) * ATTS + sp;
    if (tig == 0) {
        g_pm[p_lo] = m_lo; g_pl[p_lo] = l_lo;
        g_pm[p_hi] = m_hi; g_pl[p_hi] = l_hi;
    }
#pragma unroll
    for (int ng = 0; ng < 5; ng++) {
#pragma unroll
        for (int cc2 = 0; cc2 < 2; cc2++) {
            int cidx = ng * 8 + 2 * tig + cc2;
            float v_lo = O[ng][cc2];
            float v_hi = O[ng][2 + cc2];
            if (cidx < CC) {
                g_po[p_lo * CC + cidx] = v_lo;
                g_po[p_hi * CC + cidx] = v_hi;
            } else {
                g_pg[p_lo * (PVN * 3) + cidx - CC] = v_lo;
                g_pg[p_hi * (PVN * 3) + cidx - CC] = v_hi;
            }
        }
    }
}

// ---------------------------------------------------------------------------
// Combine + finalize fused: block handles 16 rows. float4 partial loads.
// ---------------------------------------------------------------------------
#define RPB 16
__global__ void combine_finalize_kernel(const float* __restrict__ bupd,
                                        float* __restrict__ out) {
    __shared__ float soc[RPB][OCW];
    int tid = threadIdx.x;
    int row0 = blockIdx.x * RPB;

    if (tid < RPB * HH) {
        int r = tid / HH;
        int h = tid % HH;
        int row = row0 + r;
        int p0 = (row * HH + h) * ATTS;

        float m = -1e30f;
#pragma unroll
        for (int s = 0; s < ATTS; s++) m = fmaxf(m, g_pm[p0 + s]);
        float L = 0.f;
        float o[CC], g[PVN * 3];
#pragma unroll
        for (int c = 0; c < CC; c++) o[c] = 0.f;
#pragma unroll
        for (int x = 0; x < PVN * 3; x++) g[x] = 0.f;
#pragma unroll
        for (int s = 0; s < ATTS; s++) {
            float w = __expf(g_pm[p0 + s] - m);
            L += g_pl[p0 + s] * w;
            const float4* po4 = reinterpret_cast<const float4*>(g_po + (long)(p0 + s) * CC);
#pragma unroll
            for (int c4 = 0; c4 < CC / 4; c4++) {
                float4 v = po4[c4];
                o[c4*4+0] += w * v.x; o[c4*4+1] += w * v.y;
                o[c4*4+2] += w * v.z; o[c4*4+3] += w * v.w;
            }
            const float4* pg4 = reinterpret_cast<const float4*>(g_pg + (long)(p0 + s) * (PVN * 3));
#pragma unroll
            for (int c4 = 0; c4 < PVN * 3 / 4; c4++) {
                float4 v = pg4[c4];
                g[c4*4+0] += w * v.x; g[c4*4+1] += w * v.y;
                g[c4*4+2] += w * v.z; g[c4*4+3] += w * v.w;
            }
        }
        float inv = 1.f / L;
#pragma unroll
        for (int c = 0; c < CC; c++) o[c] *= inv;
#pragma unroll
        for (int x = 0; x < PVN * 3; x++) g[x] *= inv;

        float R[9], tr[3];
#pragma unroll
        for (int r9 = 0; r9 < 9; r9++) R[r9] = g_rP[row * 9 + r9];
#pragma unroll
        for (int r3 = 0; r3 < 3; r3++) tr[r3] = g_tP[row * 3 + r3];

#pragma unroll
        for (int c = 0; c < CC; c++) soc[r][h * CC + c] = o[c];
#pragma unroll
        for (int pp = 0; pp < PVN; pp++) {
            float gx = g[pp * 3 + 0] - tr[0];
            float gy = g[pp * 3 + 1] - tr[1];
            float gz = g[pp * 3 + 2] - tr[2];
            float lx = R[0] * gx + R[3] * gy + R[6] * gz;
            float ly = R[1] * gx + R[4] * gy + R[7] * gz;
            float lz = R[2] * gx + R[5] * gy + R[8] * gz;
            soc[r][HC + h * PVN * 3 + pp * 3 + 0] = lx;
            soc[r][HC + h * PVN * 3 + pp * 3 + 1] = ly;
            soc[r][HC + h * PVN * 3 + pp * 3 + 2] = lz;
            soc[r][HC + HPV3 + h * PVN + pp] =
                sqrtf(lx * lx + ly * ly + lz * lz + 1e-8f);
        }
    }
    __syncthreads();

    int warp = tid >> 5;
    int lane = tid & 31;
    int row = row0 + warp;

    float acc[6] = {0.f, 0.f, 0.f, 0.f, 0.f, 0.f};
    for (int k = lane; k < OCW; k += 32) {
        float v = soc[warp][k];
#pragma unroll
        for (int j = 0; j < 6; j++) acc[j] += v * g_wfold[j * OCW + k];
    }
#pragma unroll
    for (int off = 16; off > 0; off >>= 1)
#pragma unroll
        for (int j = 0; j < 6; j++)
            acc[j] += __shfl_down_sync(0xffffffffu, acc[j], off);
    if (lane != 0) return;

    float u[6];
#pragma unroll
    for (int j = 0; j < 6; j++) u[j] = acc[j] + bupd[j];

    float bq = u[0], cq = u[1], dq = u[2];
    float ninv = rsqrtf(1.f + bq * bq + cq * cq + dq * dq);
    float w = ninv, x = bq * ninv, y = cq * ninv, z = dq * ninv;
    float Ru[9];
    Ru[0] = 1.f - 2.f * (y * y + z * z); Ru[1] = 2.f * (x * y - w * z); Ru[2] = 2.f * (x * z + w * y);
    Ru[3] = 2.f * (x * y + w * z); Ru[4] = 1.f - 2.f * (x * x + z * z); Ru[5] = 2.f * (y * z - w * x);
    Ru[6] = 2.f * (x * z - w * y); Ru[7] = 2.f * (y * z + w * x); Ru[8] = 1.f - 2.f * (x * x + y * y);

    float R[9];
#pragma unroll
    for (int r = 0; r < 9; r++) R[r] = g_rP[row * 9 + r];

    float Rn[9];
#pragma unroll
    for (int r = 0; r < 3; r++)
#pragma unroll
        for (int c = 0; c < 3; c++) {
            float a = 0.f;
#pragma unroll
            for (int k = 0; k < 3; k++) a += R[r * 3 + k] * Ru[k * 3 + c];
            Rn[r * 3 + c] = a;
        }

    out[row * 3 + 0] = R[0] * u[3] + R[1] * u[4] + R[2] * u[5] + g_tP[row * 3 + 0];
    out[row * 3 + 1] = R[3] * u[3] + R[4] * u[4] + R[5] * u[5] + g_tP[row * 3 + 1];
    out[row * 3 + 2] = R[6] * u[3] + R[7] * u[4] + R[8] * u[5] + g_tP[row * 3 + 2];
    float* rout = out + BB * PROW * 3;
#pragma unroll
    for (int r = 0; r < 9; r++) rout[row * 9 + r] = Rn[r];
}

// ---------------------------------------------------------------------------
extern "C" void kernel_launch(void* const* d_in, const int* in_sizes, int n_in,
                              void* d_out, int out_size) {
    const float* trans = (const float*)d_in[0];
    const float* rots  = (const float*)d_in[1];
    const float* s     = (const float*)d_in[2];
    const float* wq    = (const float*)d_in[3];
    const float* wk    = (const float*)d_in[4];
    const float* wv    = (const float*)d_in[5];
    const float* wqp   = (const float*)d_in[6];
    const float* wkp   = (const float*)d_in[7];
    const float* wvp   = (const float*)d_in[8];
    const float* gamma = (const float*)d_in[9];
    const float* wout  = (const float*)d_in[10];
    const float* wupd  = (const float*)d_in[11];
    const float* bupd  = (const float*)d_in[12];
    float* out = (float*)d_out;

    float *p_s_pool, *p_k0, *p_v0, *p_kp0, *p_vp0, *p_q, *p_qp;
    cudaGetSymbolAddress((void**)&p_s_pool, g_s_pool);
    cudaGetSymbolAddress((void**)&p_k0, g_k0);
    cudaGetSymbolAddress((void**)&p_v0, g_v0);
    cudaGetSymbolAddress((void**)&p_kp0, g_kp0);
    cudaGetSymbolAddress((void**)&p_vp0, g_vp0);
    cudaGetSymbolAddress((void**)&p_q, g_q);
    cudaGetSymbolAddress((void**)&p_qp, g_qp);

    // 1. prep + weight fold (fused)
    prep_fold_kernel<<<(SP_TOT + TRP_TOT + FOLD_TOT + 255) / 256, 256>>>(
        s, trans, rots, wout, wupd);

    // 2. projection GEMMs (tf32 tensor cores)
    TaskPack P;
    int Mraw = BB * NN;
    int Mpool = BB * PROW;
    auto setTask = [&](int ti, const float* A, const float* B, float* C,
                       int M, int N, int K) {
        P.t[ti].A = A; P.t[ti].B = B; P.t[ti].C = C;
        P.t[ti].M = M; P.t[ti].N = N; P.t[ti].K = K;
        P.t[ti].gx = (N + GBN - 1) / GBN;
    };
    setTask(0, s, wk,  p_k0,  Mraw, HC,   CSD);
    setTask(1, s, wv,  p_v0,  Mraw, HC,   CSD);
    setTask(2, s, wkp, p_kp0, Mraw, HPQ3, CSD);
    setTask(3, s, wvp, p_vp0, Mraw, HPV3, CSD);
    setTask(4, p_s_pool, wq,  p_q,  Mpool, HC,   CSD);
    setTask(5, p_s_pool, wqp, p_qp, Mpool, HPQ3, CSD);
    P.ofs[0] = 0;
    for (int ti = 0; ti < NTASK; ti++) {
        int gy = (P.t[ti].M + GBM - 1) / GBM;
        P.ofs[ti + 1] = P.ofs[ti] + P.t[ti].gx * gy;
    }
    mgemm_kernel<<<P.ofs[NTASK], 256>>>(P);

    // 3. transforms
    transform_kernel<<<(XF_TOT + 255) / 256, 256>>>(trans, rots);

    // 4. tensor-core flash attention
    attn_mma_kernel<<<dim3(BB * HH, PROW / 64, ATTS), 128>>>(gamma);

    // 5. combine + finalize (fused)
    combine_finalize_kernel<<<(BB * PROW) / RPB, RPB * 32>>>(bupd, out);
}

// round 16
// speedup vs baseline: 1.8553x; 1.0533x over previous
#include <cuda_runtime.h>
#include <math.h>

// Problem constants
#define BB 2
#define NN 1024
#define CSD 384
#define HH 12
#define CC 16
#define PQN 4
#define PVN 8
#define NPAD 1026        // N + 2*PAD
#define PROW 512         // num_pool
#define TT 1538          // NPAD + PROW
#define HC 192           // H*C
#define HPQ3 144         // H*PQ*3
#define HPV3 288         // H*PV*3
#define OCW 576          // HC + HPV3 + H*PV
#define ATTS 4           // split-KV factor
#define ACHUNK ((TT + ATTS - 1) / ATTS)   // 385
#define KED 32           // extended key dim (16 k + 12 kg + sk + 3 pad)
#define VED 40           // extended value dim (16 v + 24 vg)
#define TJ 32            // keys per tile

#define C1 0.176776695f       // w_l * (1/sqrt(C))
#define WC_HALF 0.117851130f  // w_c/2

typedef unsigned long long u64;

__device__ __forceinline__ unsigned f2tf32(float v) {
    unsigned r; asm("cvt.rna.tf32.f32 %0, %1;" : "=r"(r) : "f"(v)); return r;
}
__device__ __forceinline__ void mma_tf32(float* d, unsigned a0, unsigned a1,
                                         unsigned a2, unsigned a3,
                                         unsigned b0, unsigned b1) {
    asm volatile(
        "mma.sync.aligned.m16n8k8.row.col.f32.tf32.tf32.f32 "
        "{%0,%1,%2,%3}, {%4,%5,%6,%7}, {%8,%9}, {%0,%1,%2,%3};"
        : "+f"(d[0]), "+f"(d[1]), "+f"(d[2]), "+f"(d[3])
        : "r"(a0), "r"(a1), "r"(a2), "r"(a3), "r"(b0), "r"(b1));
}

// Scratch (device globals)
__device__ float g_s_pool[BB*PROW*CSD];
__device__ float g_tP[BB*PROW*3];
__device__ float g_rP[BB*PROW*9];
__device__ float g_k0 [BB*NN*HC];
__device__ float g_v0 [BB*NN*HC];
__device__ float g_kp0[BB*NN*HPQ3];
__device__ float g_vp0[BB*NN*HPV3];
__device__ float g_q  [BB*PROW*HC];
__device__ float g_qp [BB*PROW*HPQ3];
__device__ float g_wfold[6*OCW];
// packed tf32 extended keys/values, layout [b][t][h][dim]
__device__ unsigned g_ke[(long)BB*TT*HH*KED];
__device__ unsigned g_ve[(long)BB*TT*HH*VED];

#define NPART (BB*PROW*HH*ATTS)
__device__ float g_pm[NPART];
__device__ float g_pl[NPART];
__device__ float g_po[NPART*CC];
__device__ float g_pg[NPART*PVN*3];

__device__ __forceinline__ int clampsrc(int e) {
    int v = e - 1;
    return v < 0 ? 0 : (v > NN - 1 ? NN - 1 : v);
}

// ---------------------------------------------------------------------------
// Prep + weight fold fused
// ---------------------------------------------------------------------------
#define SP_TOT (BB*PROW*CSD)
#define TRP_TOT (BB*PROW*12)
#define FOLD_TOT (OCW*32)
__global__ void prep_fold_kernel(const float* __restrict__ s,
                                 const float* __restrict__ trans,
                                 const float* __restrict__ rots,
                                 const float* __restrict__ wout,
                                 const float* __restrict__ wupd) {
    int idx = blockIdx.x * blockDim.x + threadIdx.x;
    if (idx < SP_TOT) {
        int c = idx % CSD;
        int bp = idx / CSD;
        int p = bp % PROW;
        int b = bp / PROW;
        g_s_pool[idx] = (s[(b * NN + clampsrc(2 * p    )) * CSD + c]
                       + s[(b * NN + clampsrc(2 * p + 1)) * CSD + c]
                       + s[(b * NN + clampsrc(2 * p + 2)) * CSD + c]) * (1.f / 3.f);
        return;
    }
    int k = idx - SP_TOT;
    if (k < TRP_TOT) {
        int d = k % 12;
        int bp = k / 12;
        int p = bp % PROW;
        int b = bp / PROW;
        int r0 = clampsrc(2 * p), r1 = clampsrc(2 * p + 1), r2 = clampsrc(2 * p + 2);
        if (d < 3) {
            g_tP[bp * 3 + d] = (trans[(b * NN + r0) * 3 + d]
                              + trans[(b * NN + r1) * 3 + d]
                              + trans[(b * NN + r2) * 3 + d]) * (1.f / 3.f);
        } else {
            int r = d - 3;
            g_rP[bp * 9 + r] = (rots[(b * NN + r0) * 9 + r]
                              + rots[(b * NN + r1) * 9 + r]
                              + rots[(b * NN + r2) * 9 + r]) * (1.f / 3.f);
        }
        return;
    }
    int fi = k - TRP_TOT;
    if (fi >= FOLD_TOT) return;
    int gw = fi >> 5;
    int lane = fi & 31;
    const float* wr = wout + (long)gw * CSD;
    float acc[6] = {0, 0, 0, 0, 0, 0};
    for (int m = lane; m < CSD; m += 32) {
        float w = wr[m];
#pragma unroll
        for (int j = 0; j < 6; j++) acc[j] += w * __ldg(&wupd[m * 6 + j]);
    }
#pragma unroll
    for (int off = 16; off > 0; off >>= 1)
#pragma unroll
        for (int j = 0; j < 6; j++)
            acc[j] += __shfl_down_sync(0xffffffffu, acc[j], off);
    if (lane == 0) {
#pragma unroll
        for (int j = 0; j < 6; j++) g_wfold[j * OCW + gw] = acc[j];
    }
}

// ---------------------------------------------------------------------------
// Fused multi-task GEMM on tensor cores (tf32 mma m16n8k8) — proven.
// ---------------------------------------------------------------------------
#define NTASK 6
struct GemmTask {
    const float* A;
    const float* B;
    float* C;
    int M, N, K, gx;
};
struct TaskPack {
    GemmTask t[NTASK];
    int ofs[NTASK + 1];
};

#define GBM 64
#define GBN 64
#define GBK 16
__global__ void mgemm_kernel(TaskPack P) {
    int bid = blockIdx.x;
    int ti = 0;
#pragma unroll
    for (int x = 0; x < NTASK - 1; x++)
        if (bid >= P.ofs[x + 1]) ti = x + 1;
    GemmTask tk = P.t[ti];
    int lb = bid - P.ofs[ti];
    int bx = lb % tk.gx, by = lb / tk.gx;

    __shared__ unsigned As[GBM][GBK + 1];
    __shared__ unsigned Bs[GBK][GBN + 8];

    int tid = threadIdx.x;
    int warp = tid >> 5, lane = tid & 31;
    int gid = lane >> 2, tig = lane & 3;
    int wm = warp & 3;
    int wn = warp >> 2;
    int row0 = by * GBM;
    int col0 = bx * GBN;
    const float* A = tk.A;
    const float* Bm = tk.B;
    int M = tk.M, Nn = tk.N, K = tk.K;

    float d[4][4];
#pragma unroll
    for (int t = 0; t < 4; t++)
#pragma unroll
        for (int c = 0; c < 4; c++) d[t][c] = 0.f;

    for (int k0 = 0; k0 < K; k0 += GBK) {
#pragma unroll
        for (int x = 0; x < 4; x++) {
            int li = tid + x * 256;
            int m = li >> 4, kk = li & 15;
            int gm = row0 + m;
            float v = (gm < M) ? A[(long)gm * K + k0 + kk] : 0.f;
            As[m][kk] = f2tf32(v);
        }
#pragma unroll
        for (int x = 0; x < 4; x++) {
            int li = tid + x * 256;
            int kk = li >> 6, n = li & 63;
            int gn = col0 + n;
            float v = (gn < Nn) ? Bm[(long)(k0 + kk) * Nn + gn] : 0.f;
            Bs[kk][n] = f2tf32(v);
        }
        __syncthreads();

#pragma unroll
        for (int ks = 0; ks < 2; ks++) {
            int kb = ks * 8;
            int ra = wm * 16 + gid;
            unsigned a0 = As[ra][kb + tig];
            unsigned a1 = As[ra + 8][kb + tig];
            unsigned a2 = As[ra][kb + tig + 4];
            unsigned a3 = As[ra + 8][kb + tig + 4];
#pragma unroll
            for (int t = 0; t < 4; t++) {
                int nb = wn * 32 + t * 8;
                unsigned b0 = Bs[kb + tig][nb + gid];
                unsigned b1 = Bs[kb + tig + 4][nb + gid];
                mma_tf32(d[t], a0, a1, a2, a3, b0, b1);
            }
        }
        __syncthreads();
    }

#pragma unroll
    for (int t = 0; t < 4; t++) {
        int gn0 = col0 + wn * 32 + t * 8 + tig * 2;
        int gm0 = row0 + wm * 16 + gid;
        if (gm0 < M) {
            if (gn0 < Nn)     tk.C[(long)gm0 * Nn + gn0]     = d[t][0];
            if (gn0 + 1 < Nn) tk.C[(long)gm0 * Nn + gn0 + 1] = d[t][1];
        }
        int gm1 = gm0 + 8;
        if (gm1 < M) {
            if (gn0 < Nn)     tk.C[(long)gm1 * Nn + gn0]     = d[t][2];
            if (gn0 + 1 < Nn) tk.C[(long)gm1 * Nn + gn0 + 1] = d[t][3];
        }
    }
}

// ---------------------------------------------------------------------------
// Transform + pack: builds tf32 KE/VE rows directly.
//  R1 (b,n,h): raw rows -> KE/VE at jj=n+1 (+ edge dupes jj=0, jj=NPAD-1)
//  R2 (b,p,h): pooled rows (avg + rotate) -> KE/VE at jj=NPAD+p
//  R3 (b,p,h): q point transform (in place)
// KE row: [tf32 k(16) | tf32 kg(12) | sk fp32 bits | 0 0 0]
// VE row: [tf32 v(16) | tf32 vg(24)]
// ---------------------------------------------------------------------------
#define RAWPT (BB*NN*HH)
#define POOLPT (BB*PROW*HH)
#define QPT (BB*PROW*HH)
#define XF_TOT (RAWPT + POOLPT + QPT)

__device__ __forceinline__ float4 avg3f4(float4 a, float4 b, float4 c) {
    return make_float4((a.x + b.x + c.x) * (1.f / 3.f),
                       (a.y + b.y + c.y) * (1.f / 3.f),
                       (a.z + b.z + c.z) * (1.f / 3.f),
                       (a.w + b.w + c.w) * (1.f / 3.f));
}

__device__ __forceinline__ void write_kerow(long rowbase, const float* kf,
                                            const float* gp, float sk) {
    unsigned* dst = g_ke + rowbase * KED;
#pragma unroll
    for (int c = 0; c < 4; c++) {
        uint4 u;
        u.x = f2tf32(kf[c*4+0]); u.y = f2tf32(kf[c*4+1]);
        u.z = f2tf32(kf[c*4+2]); u.w = f2tf32(kf[c*4+3]);
        *reinterpret_cast<uint4*>(dst + c * 4) = u;
    }
#pragma unroll
    for (int c = 0; c < 3; c++) {
        uint4 u;
        u.x = f2tf32(gp[c*4+0]); u.y = f2tf32(gp[c*4+1]);
        u.z = f2tf32(gp[c*4+2]); u.w = f2tf32(gp[c*4+3]);
        *reinterpret_cast<uint4*>(dst + 16 + c * 4) = u;
    }
    uint4 t;
    t.x = __float_as_uint(sk); t.y = 0; t.z = 0; t.w = 0;
    *reinterpret_cast<uint4*>(dst + 28) = t;
}

__device__ __forceinline__ void write_verow(long rowbase, const float* vf,
                                            const float* gp) {
    unsigned* dst = g_ve + rowbase * VED;
#pragma unroll
    for (int c = 0; c < 4; c++) {
        uint4 u;
        u.x = f2tf32(vf[c*4+0]); u.y = f2tf32(vf[c*4+1]);
        u.z = f2tf32(vf[c*4+2]); u.w = f2tf32(vf[c*4+3]);
        *reinterpret_cast<uint4*>(dst + c * 4) = u;
    }
#pragma unroll
    for (int c = 0; c < 6; c++) {
        uint4 u;
        u.x = f2tf32(gp[c*4+0]); u.y = f2tf32(gp[c*4+1]);
        u.z = f2tf32(gp[c*4+2]); u.w = f2tf32(gp[c*4+3]);
        *reinterpret_cast<uint4*>(dst + 16 + c * 4) = u;
    }
}

__global__ void transform_kernel(const float* __restrict__ trans,
                                 const float* __restrict__ rots) {
    int idx = blockIdx.x * blockDim.x + threadIdx.x;
    if (idx < RAWPT) {
        int h = idx % HH;
        int rn = idx / HH;          // b*NN + n
        int n = rn % NN;
        int b = rn / NN;
        float R[9], tr[3];
#pragma unroll
        for (int r = 0; r < 9; r++) R[r] = rots[rn * 9 + r];
#pragma unroll
        for (int r = 0; r < 3; r++) tr[r] = trans[rn * 3 + r];

        float kf[CC], vf[CC], kg[12], vg[24];
        {
            const float4* ksrc = reinterpret_cast<const float4*>(g_k0 + ((long)rn * HC + h * CC));
            const float4* vsrc = reinterpret_cast<const float4*>(g_v0 + ((long)rn * HC + h * CC));
#pragma unroll
            for (int c = 0; c < 4; c++) {
                float4 kv = ksrc[c], vv = vsrc[c];
                kf[c*4+0]=kv.x; kf[c*4+1]=kv.y; kf[c*4+2]=kv.z; kf[c*4+3]=kv.w;
                vf[c*4+0]=vv.x; vf[c*4+1]=vv.y; vf[c*4+2]=vv.z; vf[c*4+3]=vv.w;
            }
        }
        float sk = 0.f;
        {
            const float4* src = reinterpret_cast<const float4*>(g_kp0 + ((long)rn * HPQ3 + h * 12));
            float lp[12];
#pragma unroll
            for (int c = 0; c < 3; c++) {
                float4 v = src[c];
                lp[c*4+0]=v.x; lp[c*4+1]=v.y; lp[c*4+2]=v.z; lp[c*4+3]=v.w;
            }
#pragma unroll
            for (int p = 0; p < PQN; p++) {
                float lx=lp[p*3+0], ly=lp[p*3+1], lz=lp[p*3+2];
                float gx=R[0]*lx+R[1]*ly+R[2]*lz+tr[0];
                float gy=R[3]*lx+R[4]*ly+R[5]*lz+tr[1];
                float gz=R[6]*lx+R[7]*ly+R[8]*lz+tr[2];
                kg[p*3+0]=gx; kg[p*3+1]=gy; kg[p*3+2]=gz;
                sk += gx*gx+gy*gy+gz*gz;
            }
        }
        {
            const float4* src = reinterpret_cast<const float4*>(g_vp0 + ((long)rn * HPV3 + h * 24));
            float lp[24];
#pragma unroll
            for (int c = 0; c < 6; c++) {
                float4 v = src[c];
                lp[c*4+0]=v.x; lp[c*4+1]=v.y; lp[c*4+2]=v.z; lp[c*4+3]=v.w;
            }
#pragma unroll
            for (int p = 0; p < PVN; p++) {
                float lx=lp[p*3+0], ly=lp[p*3+1], lz=lp[p*3+2];
                vg[p*3+0]=R[0]*lx+R[1]*ly+R[2]*lz+tr[0];
                vg[p*3+1]=R[3]*lx+R[4]*ly+R[5]*lz+tr[1];
                vg[p*3+2]=R[6]*lx+R[7]*ly+R[8]*lz+tr[2];
            }
        }
        long base = ((long)b * TT) * HH + h;   // row index formula: ((b*TT + jj)*HH + h)
        long row1 = base + (long)(n + 1) * HH;
        write_kerow(row1, kf, kg, sk);
        write_verow(row1, vf, vg);
        if (n == 0) {
            write_kerow(base, kf, kg, sk);
            write_verow(base, vf, vg);
        }
        if (n == NN - 1) {
            long rowe = base + (long)(NPAD - 1) * HH;
            write_kerow(rowe, kf, kg, sk);
            write_verow(rowe, vf, vg);
        }
        return;
    }
    int i2 = idx - RAWPT;
    if (i2 < POOLPT) {
        int h = i2 % HH;
        int rp = i2 / HH;
        int p = rp % PROW;
        int b = rp / PROW;
        int r0 = clampsrc(2 * p), r1 = clampsrc(2 * p + 1), r2 = clampsrc(2 * p + 2);
        float R[9], tr[3];
#pragma unroll
        for (int r = 0; r < 9; r++) R[r] = g_rP[rp * 9 + r];
#pragma unroll
        for (int r = 0; r < 3; r++) tr[r] = g_tP[rp * 3 + r];

        float kf[CC], vf[CC], kg[12], vg[24];
#pragma unroll
        for (int c = 0; c < 4; c++) {
            float4 a = reinterpret_cast<const float4*>(g_k0 + ((long)(b*NN+r0)*HC + h*CC))[c];
            float4 bb = reinterpret_cast<const float4*>(g_k0 + ((long)(b*NN+r1)*HC + h*CC))[c];
            float4 cc = reinterpret_cast<const float4*>(g_k0 + ((long)(b*NN+r2)*HC + h*CC))[c];
            float4 v = avg3f4(a, bb, cc);
            kf[c*4+0]=v.x; kf[c*4+1]=v.y; kf[c*4+2]=v.z; kf[c*4+3]=v.w;
            float4 a2 = reinterpret_cast<const float4*>(g_v0 + ((long)(b*NN+r0)*HC + h*CC))[c];
            float4 b2 = reinterpret_cast<const float4*>(g_v0 + ((long)(b*NN+r1)*HC + h*CC))[c];
            float4 c2 = reinterpret_cast<const float4*>(g_v0 + ((long)(b*NN+r2)*HC + h*CC))[c];
            float4 v2 = avg3f4(a2, b2, c2);
            vf[c*4+0]=v2.x; vf[c*4+1]=v2.y; vf[c*4+2]=v2.z; vf[c*4+3]=v2.w;
        }
        float sk = 0.f;
        {
            float lp[12];
#pragma unroll
            for (int c = 0; c < 3; c++) {
                float4 a = reinterpret_cast<const float4*>(g_kp0 + ((long)(b*NN+r0)*HPQ3 + h*12))[c];
                float4 bb = reinterpret_cast<const float4*>(g_kp0 + ((long)(b*NN+r1)*HPQ3 + h*12))[c];
                float4 cc = reinterpret_cast<const float4*>(g_kp0 + ((long)(b*NN+r2)*HPQ3 + h*12))[c];
                float4 v = avg3f4(a, bb, cc);
                lp[c*4+0]=v.x; lp[c*4+1]=v.y; lp[c*4+2]=v.z; lp[c*4+3]=v.w;
            }
#pragma unroll
            for (int pp = 0; pp < PQN; pp++) {
                float lx=lp[pp*3+0], ly=lp[pp*3+1], lz=lp[pp*3+2];
                float gx=R[0]*lx+R[1]*ly+R[2]*lz+tr[0];
                float gy=R[3]*lx+R[4]*ly+R[5]*lz+tr[1];
                float gz=R[6]*lx+R[7]*ly+R[8]*lz+tr[2];
                kg[pp*3+0]=gx; kg[pp*3+1]=gy; kg[pp*3+2]=gz;
                sk += gx*gx+gy*gy+gz*gz;
            }
        }
        {
            float lp[24];
#pragma unroll
            for (int c = 0; c < 6; c++) {
                float4 a = reinterpret_cast<const float4*>(g_vp0 + ((long)(b*NN+r0)*HPV3 + h*24))[c];
                float4 bb = reinterpret_cast<const float4*>(g_vp0 + ((long)(b*NN+r1)*HPV3 + h*24))[c];
                float4 cc = reinterpret_cast<const float4*>(g_vp0 + ((long)(b*NN+r2)*HPV3 + h*24))[c];
                float4 v = avg3f4(a, bb, cc);
                lp[c*4+0]=v.x; lp[c*4+1]=v.y; lp[c*4+2]=v.z; lp[c*4+3]=v.w;
            }
#pragma unroll
            for (int pp = 0; pp < PVN; pp++) {
                float lx=lp[pp*3+0], ly=lp[pp*3+1], lz=lp[pp*3+2];
                vg[pp*3+0]=R[0]*lx+R[1]*ly+R[2]*lz+tr[0];
                vg[pp*3+1]=R[3]*lx+R[4]*ly+R[5]*lz+tr[1];
                vg[pp*3+2]=R[6]*lx+R[7]*ly+R[8]*lz+tr[2];
            }
        }
        long row = ((long)(b * TT + NPAD + p)) * HH + h;
        write_kerow(row, kf, kg, sk);
        write_verow(row, vf, vg);
        return;
    }
    int i4 = i2 - POOLPT;
    if (i4 >= QPT) return;
    int h = i4 % HH;
    int rp = i4 / HH;
    float R[9], tr[3];
#pragma unroll
    for (int r = 0; r < 9; r++) R[r] = g_rP[rp * 9 + r];
#pragma unroll
    for (int r = 0; r < 3; r++) tr[r] = g_tP[rp * 3 + r];
    float lp[12];
    float4* qp4 = reinterpret_cast<float4*>(g_qp + ((long)rp * HPQ3 + h * 12));
#pragma unroll
    for (int c = 0; c < 3; c++) {
        float4 v = qp4[c];
        lp[c*4+0]=v.x; lp[c*4+1]=v.y; lp[c*4+2]=v.z; lp[c*4+3]=v.w;
    }
    float gp[12];
#pragma unroll
    for (int p = 0; p < PQN; p++) {
        float lx=lp[p*3+0], ly=lp[p*3+1], lz=lp[p*3+2];
        gp[p*3+0]=R[0]*lx+R[1]*ly+R[2]*lz+tr[0];
        gp[p*3+1]=R[3]*lx+R[4]*ly+R[5]*lz+tr[1];
        gp[p*3+2]=R[6]*lx+R[7]*ly+R[8]*lz+tr[2];
    }
#pragma unroll
    for (int c = 0; c < 3; c++)
        qp4[c] = make_float4(gp[c*4+0], gp[c*4+1], gp[c*4+2], gp[c*4+3]);
}

// ---------------------------------------------------------------------------
// Tensor-core flash attention, packed KE/VE loads (branch-free uint4 copies).
// Block = 128 threads = 4 warps, 16 queries/warp. grid (B*H, PROW/64, ATTS).
// ---------------------------------------------------------------------------
__global__ void attn_mma_kernel(const float* __restrict__ gamma) {
    __shared__ unsigned qe_s[4][16][36];
    __shared__ unsigned ke_s[TJ][36];
    __shared__ unsigned ve_s[TJ][44];
    __shared__ unsigned p_s[4][16][36];

    int bh = blockIdx.x;
    int b = bh / HH, h = bh % HH;
    int sp = blockIdx.z;
    int tid = threadIdx.x;
    int warp = tid >> 5, lane = tid & 31;
    int gid = lane >> 2, tig = lane & 3;

    int j_begin = sp * ACHUNK;
    int j_end = j_begin + ACHUNK;
    if (j_end > TT) j_end = TT;

    float gm = gamma[h];
    float gco = logf(1.f + __expf(gm)) * WC_HALF;

    int qbase = blockIdx.y * 64 + warp * 16;

    // Build QE (16 x 32): [C1*q | 2g*qp | 0 0 0 0]
    for (int idx = lane; idx < 16 * 32; idx += 32) {
        int r = idx >> 5, c = idx & 31;
        long qrow = (long)(b * PROW + qbase + r);
        float v = 0.f;
        if (c < 16) v = C1 * g_q[qrow * HC + h * CC + c];
        else if (c < 28) v = 2.f * gco * g_qp[qrow * HPQ3 + h * 12 + (c - 16)];
        qe_s[warp][r][c] = f2tf32(v);
    }
    __syncwarp();

    long kvbase = (long)b * TT;   // row = (kvbase + jj)*HH + h

    float S[4][4];
    float O[5][4];
#pragma unroll
    for (int n = 0; n < 5; n++)
#pragma unroll
        for (int c = 0; c < 4; c++) O[n][c] = 0.f;
    float m_lo = -1e30f, m_hi = -1e30f, l_lo = 0.f, l_hi = 0.f;

    for (int j0 = j_begin; j0 < j_end; j0 += TJ) {
        __syncthreads();
        // KE tile: branch-free uint4 copies
        for (int x = tid; x < TJ * 8; x += 128) {
            int j = x >> 3, c4 = x & 7;
            int jj = j0 + j;
            uint4 u = make_uint4(0, 0, 0, 0);
            if (jj < j_end)
                u = *reinterpret_cast<const uint4*>(
                    g_ke + ((kvbase + jj) * HH + h) * KED + c4 * 4);
            *reinterpret_cast<uint4*>(&ke_s[j][c4 * 4]) = u;
        }
        // VE tile
        for (int x = tid; x < TJ * 10; x += 128) {
            int j = x / 10, c4 = x % 10;
            int jj = j0 + j;
            uint4 u = make_uint4(0, 0, 0, 0);
            if (jj < j_end)
                u = *reinterpret_cast<const uint4*>(
                    g_ve + ((kvbase + jj) * HH + h) * VED + c4 * 4);
            *reinterpret_cast<uint4*>(&ve_s[j][c4 * 4]) = u;
        }
        __syncthreads();

        // S = QE x KE^T
#pragma unroll
        for (int g4 = 0; g4 < 4; g4++)
            S[g4][0] = S[g4][1] = S[g4][2] = S[g4][3] = 0.f;
#pragma unroll
        for (int ks = 0; ks < 4; ks++) {
            unsigned a0 = qe_s[warp][gid][ks * 8 + tig];
            unsigned a1 = qe_s[warp][gid + 8][ks * 8 + tig];
            unsigned a2 = qe_s[warp][gid][ks * 8 + tig + 4];
            unsigned a3 = qe_s[warp][gid + 8][ks * 8 + tig + 4];
#pragma unroll
            for (int g4 = 0; g4 < 4; g4++) {
                unsigned b0 = ke_s[g4 * 8 + gid][ks * 8 + tig];
                unsigned b1 = ke_s[g4 * 8 + gid][ks * 8 + tig + 4];
                mma_tf32(S[g4], a0, a1, a2, a3, b0, b1);
            }
        }

        // add -g*sk (fp32 bits at KE slot 28), mask invalid
        float mloc_lo = -1e30f, mloc_hi = -1e30f;
#pragma unroll
        for (int g4 = 0; g4 < 4; g4++) {
            int c0 = j0 + g4 * 8 + 2 * tig;
            float nsk0 = -gco * __uint_as_float(ke_s[g4 * 8 + 2 * tig][28]);
            float nsk1 = -gco * __uint_as_float(ke_s[g4 * 8 + 2 * tig + 1][28]);
            S[g4][0] += nsk0; S[g4][1] += nsk1;
            S[g4][2] += nsk0; S[g4][3] += nsk1;
            if (c0 >= j_end)     { S[g4][0] = -1e30f; S[g4][2] = -1e30f; }
            if (c0 + 1 >= j_end) { S[g4][1] = -1e30f; S[g4][3] = -1e30f; }
            mloc_lo = fmaxf(mloc_lo, fmaxf(S[g4][0], S[g4][1]));
            mloc_hi = fmaxf(mloc_hi, fmaxf(S[g4][2], S[g4][3]));
        }
        mloc_lo = fmaxf(mloc_lo, __shfl_xor_sync(0xffffffffu, mloc_lo, 1));
        mloc_lo = fmaxf(mloc_lo, __shfl_xor_sync(0xffffffffu, mloc_lo, 2));
        mloc_hi = fmaxf(mloc_hi, __shfl_xor_sync(0xffffffffu, mloc_hi, 1));
        mloc_hi = fmaxf(mloc_hi, __shfl_xor_sync(0xffffffffu, mloc_hi, 2));

        float mn_lo = fmaxf(m_lo, mloc_lo);
        float mn_hi = fmaxf(m_hi, mloc_hi);
        float corr_lo = __expf(m_lo - mn_lo);
        float corr_hi = __expf(m_hi - mn_hi);
        m_lo = mn_lo; m_hi = mn_hi;

        float es_lo = 0.f, es_hi = 0.f;
#pragma unroll
        for (int g4 = 0; g4 < 4; g4++) {
            float e0 = __expf(S[g4][0] - m_lo);
            float e1 = __expf(S[g4][1] - m_lo);
            float e2 = __expf(S[g4][2] - m_hi);
            float e3 = __expf(S[g4][3] - m_hi);
            es_lo += e0 + e1;
            es_hi += e2 + e3;
            p_s[warp][gid][g4 * 8 + 2 * tig]         = f2tf32(e0);
            p_s[warp][gid][g4 * 8 + 2 * tig + 1]     = f2tf32(e1);
            p_s[warp][gid + 8][g4 * 8 + 2 * tig]     = f2tf32(e2);
            p_s[warp][gid + 8][g4 * 8 + 2 * tig + 1] = f2tf32(e3);
        }
        es_lo += __shfl_xor_sync(0xffffffffu, es_lo, 1);
        es_lo += __shfl_xor_sync(0xffffffffu, es_lo, 2);
        es_hi += __shfl_xor_sync(0xffffffffu, es_hi, 1);
        es_hi += __shfl_xor_sync(0xffffffffu, es_hi, 2);
        l_lo = l_lo * corr_lo + es_lo;
        l_hi = l_hi * corr_hi + es_hi;

#pragma unroll
        for (int ng = 0; ng < 5; ng++) {
            O[ng][0] *= corr_lo; O[ng][1] *= corr_lo;
            O[ng][2] *= corr_hi; O[ng][3] *= corr_hi;
        }
        __syncwarp();

        // O += P x VE
#pragma unroll
        for (int ks = 0; ks < 4; ks++) {
            unsigned a0 = p_s[warp][gid][ks * 8 + tig];
            unsigned a1 = p_s[warp][gid + 8][ks * 8 + tig];
            unsigned a2 = p_s[warp][gid][ks * 8 + tig + 4];
            unsigned a3 = p_s[warp][gid + 8][ks * 8 + tig + 4];
#pragma unroll
            for (int ng = 0; ng < 5; ng++) {
                unsigned b0 = ve_s[ks * 8 + tig][ng * 8 + gid];
                unsigned b1 = ve_s[ks * 8 + tig + 4][ng * 8 + gid];
                mma_tf32(O[ng], a0, a1, a2, a3, b0, b1);
            }
        }
    }

    // write partials
    long qrow_lo = (long)(b * PROW + qbase + gid);
    long qrow_hi = qrow_lo + 8;
    long p_lo = (qrow_lo * HH + h) * ATTS + sp;
    long p_hi = (qrow_hi * HH + h) * ATTS + sp;
    if (tig == 0) {
        g_pm[p_lo] = m_lo; g_pl[p_lo] = l_lo;
        g_pm[p_hi] = m_hi; g_pl[p_hi] = l_hi;
    }
#pragma unroll
    for (int ng = 0; ng < 5; ng++) {
#pragma unroll
        for (int cc2 = 0; cc2 < 2; cc2++) {
            int cidx = ng * 8 + 2 * tig + cc2;
            float v_lo = O[ng][cc2];
            float v_hi = O[ng][2 + cc2];
            if (cidx < CC) {
                g_po[p_lo * CC + cidx] = v_lo;
                g_po[p_hi * CC + cidx] = v_hi;
            } else {
                g_pg[p_lo * (PVN * 3) + cidx - CC] = v_lo;
                g_pg[p_hi * (PVN * 3) + cidx - CC] = v_hi;
            }
        }
    }
}

// ---------------------------------------------------------------------------
// Combine + finalize fused: block handles 16 rows. float4 partial loads.
// ---------------------------------------------------------------------------
#define RPB 16
__global__ void combine_finalize_kernel(const float* __restrict__ bupd,
                                        float* __restrict__ out) {
    __shared__ float soc[RPB][OCW];
    int tid = threadIdx.x;
    int row0 = blockIdx.x * RPB;

    if (tid < RPB * HH) {
        int r = tid / HH;
        int h = tid % HH;
        int row = row0 + r;
        int p0 = (row * HH + h) * ATTS;

        float m = -1e30f;
#pragma unroll
        for (int s = 0; s < ATTS; s++) m = fmaxf(m, g_pm[p0 + s]);
        float L = 0.f;
        float o[CC], g[PVN * 3];
#pragma unroll
        for (int c = 0; c < CC; c++) o[c] = 0.f;
#pragma unroll
        for (int x = 0; x < PVN * 3; x++) g[x] = 0.f;
#pragma unroll
        for (int s = 0; s < ATTS; s++) {
            float w = __expf(g_pm[p0 + s] - m);
            L += g_pl[p0 + s] * w;
            const float4* po4 = reinterpret_cast<const float4*>(g_po + (long)(p0 + s) * CC);
#pragma unroll
            for (int c4 = 0; c4 < CC / 4; c4++) {
                float4 v = po4[c4];
                o[c4*4+0] += w * v.x; o[c4*4+1] += w * v.y;
                o[c4*4+2] += w * v.z; o[c4*4+3] += w * v.w;
            }
            const float4* pg4 = reinterpret_cast<const float4*>(g_pg + (long)(p0 + s) * (PVN * 3));
#pragma unroll
            for (int c4 = 0; c4 < PVN * 3 / 4; c4++) {
                float4 v = pg4[c4];
                g[c4*4+0] += w * v.x; g[c4*4+1] += w * v.y;
                g[c4*4+2] += w * v.z; g[c4*4+3] += w * v.w;
            }
        }
        float inv = 1.f / L;
#pragma unroll
        for (int c = 0; c < CC; c++) o[c] *= inv;
#pragma unroll
        for (int x = 0; x < PVN * 3; x++) g[x] *= inv;

        float R[9], tr[3];
#pragma unroll
        for (int r9 = 0; r9 < 9; r9++) R[r9] = g_rP[row * 9 + r9];
#pragma unroll
        for (int r3 = 0; r3 < 3; r3++) tr[r3] = g_tP[row * 3 + r3];

#pragma unroll
        for (int c = 0; c < CC; c++) soc[r][h * CC + c] = o[c];
#pragma unroll
        for (int pp = 0; pp < PVN; pp++) {
            float gx = g[pp * 3 + 0] - tr[0];
            float gy = g[pp * 3 + 1] - tr[1];
            float gz = g[pp * 3 + 2] - tr[2];
            float lx = R[0] * gx + R[3] * gy + R[6] * gz;
            float ly = R[1] * gx + R[4] * gy + R[7] * gz;
            float lz = R[2] * gx + R[5] * gy + R[8] * gz;
            soc[r][HC + h * PVN * 3 + pp * 3 + 0] = lx;
            soc[r][HC + h * PVN * 3 + pp * 3 + 1] = ly;
            soc[r][HC + h * PVN * 3 + pp * 3 + 2] = lz;
            soc[r][HC + HPV3 + h * PVN + pp] =
                sqrtf(lx * lx + ly * ly + lz * lz + 1e-8f);
        }
    }
    __syncthreads();

    int warp = tid >> 5;
    int lane = tid & 31;
    int row = row0 + warp;

    float acc[6] = {0.f, 0.f, 0.f, 0.f, 0.f, 0.f};
    for (int k = lane; k < OCW; k += 32) {
        float v = soc[warp][k];
#pragma unroll
        for (int j = 0; j < 6; j++) acc[j] += v * g_wfold[j * OCW + k];
    }
#pragma unroll
    for (int off = 16; off > 0; off >>= 1)
#pragma unroll
        for (int j = 0; j < 6; j++)
            acc[j] += __shfl_down_sync(0xffffffffu, acc[j], off);
    if (lane != 0) return;

    float u[6];
#pragma unroll
    for (int j = 0; j < 6; j++) u[j] = acc[j] + bupd[j];

    float bq = u[0], cq = u[1], dq = u[2];
    float ninv = rsqrtf(1.f + bq * bq + cq * cq + dq * dq);
    float w = ninv, x = bq * ninv, y = cq * ninv, z = dq * ninv;
    float Ru[9];
    Ru[0] = 1.f - 2.f * (y * y + z * z); Ru[1] = 2.f * (x * y - w * z); Ru[2] = 2.f * (x * z + w * y);
    Ru[3] = 2.f * (x * y + w * z); Ru[4] = 1.f - 2.f * (x * x + z * z); Ru[5] = 2.f * (y * z - w * x);
    Ru[6] = 2.f * (x * z - w * y); Ru[7] = 2.f * (y * z + w * x); Ru[8] = 1.f - 2.f * (x * x + y * y);

    float R[9];
#pragma unroll
    for (int r = 0; r < 9; r++) R[r] = g_rP[row * 9 + r];

    float Rn[9];
#pragma unroll
    for (int r = 0; r < 3; r++)
#pragma unroll
        for (int c = 0; c < 3; c++) {
            float a = 0.f;
#pragma unroll
            for (int k = 0; k < 3; k++) a += R[r * 3 + k] * Ru[k * 3 + c];
            Rn[r * 3 + c] = a;
        }

    out[row * 3 + 0] = R[0] * u[3] + R[1] * u[4] + R[2] * u[5] + g_tP[row * 3 + 0];
    out[row * 3 + 1] = R[3] * u[3] + R[4] * u[4] + R[5] * u[5] + g_tP[row * 3 + 1];
    out[row * 3 + 2] = R[6] * u[3] + R[7] * u[4] + R[8] * u[5] + g_tP[row * 3 + 2];
    float* rout = out + BB * PROW * 3;
#pragma unroll
    for (int r = 0; r < 9; r++) rout[row * 9 + r] = Rn[r];
}

// ---------------------------------------------------------------------------
extern "C" void kernel_launch(void* const* d_in, const int* in_sizes, int n_in,
                              void* d_out, int out_size) {
    const float* trans = (const float*)d_in[0];
    const float* rots  = (const float*)d_in[1];
    const float* s     = (const float*)d_in[2];
    const float* wq    = (const float*)d_in[3];
    const float* wk    = (const float*)d_in[4];
    const float* wv    = (const float*)d_in[5];
    const float* wqp   = (const float*)d_in[6];
    const float* wkp   = (const float*)d_in[7];
    const float* wvp   = (const float*)d_in[8];
    const float* gamma = (const float*)d_in[9];
    const float* wout  = (const float*)d_in[10];
    const float* wupd  = (const float*)d_in[11];
    const float* bupd  = (const float*)d_in[12];
    float* out = (float*)d_out;

    float *p_s_pool, *p_k0, *p_v0, *p_kp0, *p_vp0, *p_q, *p_qp;
    cudaGetSymbolAddress((void**)&p_s_pool, g_s_pool);
    cudaGetSymbolAddress((void**)&p_k0, g_k0);
    cudaGetSymbolAddress((void**)&p_v0, g_v0);
    cudaGetSymbolAddress((void**)&p_kp0, g_kp0);
    cudaGetSymbolAddress((void**)&p_vp0, g_vp0);
    cudaGetSymbolAddress((void**)&p_q, g_q);
    cudaGetSymbolAddress((void**)&p_qp, g_qp);

    // 1. prep + weight fold (fused)
    prep_fold_kernel<<<(SP_TOT + TRP_TOT + FOLD_TOT + 255) / 256, 256>>>(
        s, trans, rots, wout, wupd);

    // 2. projection GEMMs (tf32 tensor cores)
    TaskPack P;
    int Mraw = BB * NN;
    int Mpool = BB * PROW;
    auto setTask = [&](int ti, const float* A, const float* B, float* C,
                       int M, int N, int K) {
        P.t[ti].A = A; P.t[ti].B = B; P.t[ti].C = C;
        P.t[ti].M = M; P.t[ti].N = N; P.t[ti].K = K;
        P.t[ti].gx = (N + GBN - 1) / GBN;
    };
    setTask(0, s, wk,  p_k0,  Mraw, HC,   CSD);
    setTask(1, s, wv,  p_v0,  Mraw, HC,   CSD);
    setTask(2, s, wkp, p_kp0, Mraw, HPQ3, CSD);
    setTask(3, s, wvp, p_vp0, Mraw, HPV3, CSD);
    setTask(4, p_s_pool, wq,  p_q,  Mpool, HC,   CSD);
    setTask(5, p_s_pool, wqp, p_qp, Mpool, HPQ3, CSD);
    P.ofs[0] = 0;
    for (int ti = 0; ti < NTASK; ti++) {
        int gy = (P.t[ti].M + GBM - 1) / GBM;
        P.ofs[ti + 1] = P.ofs[ti] + P.t[ti].gx * gy;
    }
    mgemm_kernel<<<P.ofs[NTASK], 256>>>(P);

    // 3. transforms + KE/VE packing
    transform_kernel<<<(XF_TOT + 255) / 256, 256>>>(trans, rots);

    // 4. tensor-core flash attention (packed loads)
    attn_mma_kernel<<<dim3(BB * HH, PROW / 64, ATTS), 128>>>(gamma);

    // 5. combine + finalize (fused)
    combine_finalize_kernel<<<(BB * PROW) / RPB, RPB * 32>>>(bupd, out);
}